// round 12
// baseline (speedup 1.0000x reference)
#include <cuda_runtime.h>
#include <cuda_fp16.h>
#include <math.h>
#include <stdint.h>

#define BB 8
#define NN 8192
#define SS 2048
#define NSAMP 32
#define NSAMPLES (BB*SS*NSAMP)   /* 524288 */
#define NGROUPS (BB*SS)          /* 16384  */
#define NTILES (NSAMPLES/128)    /* 4096   */
#define R2 0.04f
#define BNEPS 1e-5f

typedef unsigned long long ull;

// ---------------- device scratch ----------------
__device__ float g_feat[(size_t)NSAMPLES*8];
__device__ float g_gmax[(size_t)NGROUPS*128];
__device__ float g_gmin[(size_t)NGROUPS*128];
__device__ float g_fsum[6];
__device__ float g_fmom[21];
__device__ float g_M[64*64];
__device__ float g_h1sum[64];
__device__ float g_x3sum[128], g_x3sq[128];
__device__ float g_W1s[64*6], g_b1s[64];
__device__ float g_sc2[64], g_sh2[64];
__device__ unsigned g_cnt;

// ---------------- mma.sync helpers ----------------
static __device__ __forceinline__ uint32_t smem_to_u32(const void* p) {
    uint32_t a;
    asm("{ .reg .u64 tmp; cvta.to.shared.u64 tmp, %1; cvt.u32.u64 %0, tmp; }"
        : "=r"(a) : "l"(p));
    return a;
}
static __device__ __forceinline__ uint32_t swz(uint32_t off) {
    return off ^ ((off >> 3) & 0x70);
}
static __device__ __forceinline__ void ldsm_x4(uint32_t (&a)[4], uint32_t addr) {
    asm volatile("ldmatrix.sync.aligned.m8n8.x4.shared.b16 {%0,%1,%2,%3}, [%4];"
        : "=r"(a[0]), "=r"(a[1]), "=r"(a[2]), "=r"(a[3]) : "r"(addr));
}
static __device__ __forceinline__ void ldsm_x2(uint32_t (&b)[2], uint32_t addr) {
    asm volatile("ldmatrix.sync.aligned.m8n8.x2.shared.b16 {%0,%1}, [%2];"
        : "=r"(b[0]), "=r"(b[1]) : "r"(addr));
}
static __device__ __forceinline__ void ldsm_x4_t(uint32_t (&a)[4], uint32_t addr) {
    asm volatile("ldmatrix.sync.aligned.m8n8.x4.trans.shared.b16 {%0,%1,%2,%3}, [%4];"
        : "=r"(a[0]), "=r"(a[1]), "=r"(a[2]), "=r"(a[3]) : "r"(addr));
}
static __device__ __forceinline__ void mma16816(float (&d)[4], const uint32_t (&a)[4],
                                                const uint32_t (&b)[2]) {
    asm volatile("mma.sync.aligned.m16n8k16.row.col.f32.f16.f16.f32 "
        "{%0,%1,%2,%3}, {%4,%5,%6,%7}, {%8,%9}, {%0,%1,%2,%3};"
        : "+f"(d[0]), "+f"(d[1]), "+f"(d[2]), "+f"(d[3])
        : "r"(a[0]), "r"(a[1]), "r"(a[2]), "r"(a[3]), "r"(b[0]), "r"(b[1]));
}

// ---------------- K0: zero accumulators ----------------
__global__ void k_zero() {
    int t = threadIdx.x;
    for (int i = t; i < 4096; i += 256) g_M[i] = 0.f;
    if (t < 6)  g_fsum[t] = 0.f;
    if (t < 21) g_fmom[t] = 0.f;
    if (t < 64) g_h1sum[t] = 0.f;
    if (t < 128){ g_x3sum[t] = 0.f; g_x3sq[t] = 0.f; }
    if (t == 0) g_cnt = 0u;
}

// ---------------- K1: ball query + feat + feat moments + out1 ----------------
__global__ __launch_bounds__(256) void k_ball(const float* __restrict__ xyz,
                                              const float* __restrict__ points,
                                              const int*   __restrict__ fps,
                                              float* __restrict__ out1) {
    extern __shared__ float sm[];
    float* sx = sm;
    float* sy = sm + NN;
    float* sz = sm + 2*NN;
    int*   fnd = (int*)(sm + 3*NN);

    int b = blockIdx.y;
    int qbase = blockIdx.x * 32;
    int tid = threadIdx.x;

    for (int i = tid; i < NN; i += 256) {
        sx[i] = xyz[(b*3+0)*NN + i];
        sy[i] = xyz[(b*3+1)*NN + i];
        sz[i] = xyz[(b*3+2)*NN + i];
    }
    __syncthreads();

    int w = tid >> 5, lane = tid & 31;
    int* f = fnd + w*32;
    unsigned lmask = (1u << lane) - 1u;

    float s1[6], s2[21];
    #pragma unroll
    for (int i = 0; i < 6; i++)  s1[i] = 0.f;
    #pragma unroll
    for (int i = 0; i < 21; i++) s2[i] = 0.f;

    for (int qi = 0; qi < 4; qi++) {
        int s = qbase + w*4 + qi;
        int cidx = fps[b*SS + s];
        float cx = sx[cidx], cy = sy[cidx], cz = sz[cidx];
        if (lane == 0) {
            out1[(b*3+0)*SS + s] = cx;
            out1[(b*3+1)*SS + s] = cy;
            out1[(b*3+2)*SS + s] = cz;
        }
        int cnt = 0;
        for (int chunk = 0; chunk < NN/32; chunk++) {
            int j = chunk*32 + lane;
            float dx = __fsub_rn(sx[j], cx);
            float dy = __fsub_rn(sy[j], cy);
            float dz = __fsub_rn(sz[j], cz);
            float d2 = __fadd_rn(__fadd_rn(__fmul_rn(dx,dx), __fmul_rn(dy,dy)),
                                 __fmul_rn(dz,dz));
            bool hit = (d2 <= R2);
            unsigned mask = __ballot_sync(0xffffffffu, hit);
            if (hit) {
                int pos = cnt + __popc(mask & lmask);
                if (pos < 32) f[pos] = j;
            }
            cnt += __popc(mask);
            if (cnt >= 32) break;
        }
        __syncwarp();
        int j = (lane < cnt) ? f[lane] : f[0];
        __syncwarp();

        float fx = sx[j]-cx, fy = sy[j]-cy, fz = sz[j]-cz;
        float p0 = points[(b*3+0)*NN + j];
        float p1 = points[(b*3+1)*NN + j];
        float p2 = points[(b*3+2)*NN + j];

        size_t base = ((size_t)(b*SS + s)*NSAMP + lane) * 8;
        *(float4*)(g_feat + base)     = make_float4(fx, fy, fz, p0);
        *(float4*)(g_feat + base + 4) = make_float4(p1, p2, 0.f, 0.f);

        float fv[6] = {fx, fy, fz, p0, p1, p2};
        int k = 0;
        #pragma unroll
        for (int c = 0; c < 6; c++) {
            s1[c] += fv[c];
            #pragma unroll
            for (int c2 = 0; c2 <= c; c2++) s2[k++] += fv[c]*fv[c2];
        }
    }

    __shared__ float red[27];
    if (tid < 27) red[tid] = 0.f;
    __syncthreads();
    #pragma unroll
    for (int i = 0; i < 6; i++) {
        float v = s1[i];
        for (int off = 16; off; off >>= 1) v += __shfl_down_sync(0xffffffffu, v, off);
        if (lane == 0) atomicAdd(&red[i], v);
    }
    #pragma unroll
    for (int i = 0; i < 21; i++) {
        float v = s2[i];
        for (int off = 16; off; off >>= 1) v += __shfl_down_sync(0xffffffffu, v, off);
        if (lane == 0) atomicAdd(&red[6+i], v);
    }
    __syncthreads();
    if (tid < 6)       atomicAdd(&g_fsum[tid], red[tid]);
    else if (tid < 27) atomicAdd(&g_fmom[tid-6], red[tid]);
}

// ---------------- BN1 fold helper ----------------
static __device__ __forceinline__ void bn1_fold_block(
        const float* __restrict__ W1, const float* __restrict__ g1,
        const float* __restrict__ b1, float* sW1, float* sB1,
        float* sMu, float* sC, int t) {
    if (t == 0) {
        const float inv = 1.0f / (float)NSAMPLES;
        for (int c = 0; c < 6; c++) sMu[c] = g_fsum[c]*inv;
        int k = 0;
        for (int c = 0; c < 6; c++)
            for (int c2 = 0; c2 <= c; c2++) {
                float v = g_fmom[k++]*inv; sC[c*6+c2] = v; sC[c2*6+c] = v;
            }
    }
    __syncthreads();
    if (t < 64) {
        float w[6];
        #pragma unroll
        for (int c = 0; c < 6; c++) w[c] = W1[t*6+c];
        float mean = 0.f;
        #pragma unroll
        for (int c = 0; c < 6; c++) mean += w[c]*sMu[c];
        float e2 = 0.f;
        #pragma unroll
        for (int c = 0; c < 6; c++) {
            float tt = 0.f;
            #pragma unroll
            for (int c2 = 0; c2 < 6; c2++) tt += sC[c*6+c2]*w[c2];
            e2 += w[c]*tt;
        }
        float var = fmaxf(e2 - mean*mean, 0.f);
        float sc = g1[t]*rsqrtf(var + BNEPS);
        #pragma unroll
        for (int c = 0; c < 6; c++) sW1[t*6+c] = w[c]*sc;
        sB1[t] = b1[t] - mean*sc;
    }
    __syncthreads();
}

// ---------------- K2: stats — HMMA SYRK on fp16 h1; last block computes BN2 --
// h1 tile: [128 samples][64 ch] fp16, 128B SW128 rows (identical to k_mma).
// SYRK via ldmatrix.trans: samples = k-dim. Warp w: m-tile (w>>1)*16, n-block
// (w&1)*32. Accumulators persist across the grid-stride loop; atomics once.
#define SMS_HB 4096
#define BW 65
__global__ __launch_bounds__(256) void k_stats(const float* __restrict__ W1,
                                               const float* __restrict__ g1,
                                               const float* __restrict__ b1,
                                               const float* __restrict__ W2,
                                               const float* __restrict__ g2,
                                               const float* __restrict__ b2) {
    extern __shared__ float sm[];
    char* smc = (char*)sm;
    uint32_t sbase = smem_to_u32(smc);
    float* sW1 = sm;            // 384
    float* sB1 = sm + 384;      // 64
    float* sMu = sm + 448;      // 6
    float* sC  = sm + 454;      // 36

    int t = threadIdx.x, w = t >> 5, lane = t & 31;
    bn1_fold_block(W1, g1, b1, sW1, sB1, sMu, sC, t);

    int m0 = (w >> 1)*16, n0 = (w & 1)*32;
    float acc[4][4];
    #pragma unroll
    for (int j = 0; j < 4; j++)
        #pragma unroll
        for (int i = 0; i < 4; i++) acc[j][i] = 0.f;
    float sumacc = 0.f;
    int sk = t & 63, sq = t >> 6;

    uint32_t hbB = sbase + SMS_HB;
    int q = lane >> 3, r = lane & 7;
    // A (m16k16, trans): q0:(k0-7,m0) q1:(k0-7,m0+8) q2:(k8-15,m0) q3:(k8-15,m0+8)
    uint32_t a_sw = swz((uint32_t)(( ((q>>1)&1)*8 + r)*128 + (m0 + (q&1)*8)*2));
    // B (2 n-tiles, trans): q0:(k0-7,n) q1:(k8-15,n) q2:(k0-7,n+8) q3:(k8-15,n+8)
    uint32_t b_sw0 = swz((uint32_t)(((q&1)*8 + r)*128 + (n0      + (q>>1)*8)*2));
    uint32_t b_sw1 = swz((uint32_t)(((q&1)*8 + r)*128 + (n0 + 16 + (q>>1)*8)*2));

    int srow = w*16 + (lane >> 1), kb = lane & 1;   // h-build mapping

    for (int tile = blockIdx.x; tile < NTILES; tile += gridDim.x) {
        size_t s0 = (size_t)tile * 128;
        // build fp16 h1 (identical to k_mma step A)
        {
            const float* fp = g_feat + (s0 + srow)*8;
            float4 f0 = *(const float4*)fp;
            float4 f1 = *(const float4*)(fp + 4);
            float f[6] = {f0.x, f0.y, f0.z, f0.w, f1.x, f1.y};
            #pragma unroll
            for (int m = 0; m < 4; m++) {
                uint32_t pk[4];
                #pragma unroll
                for (int qq = 0; qq < 4; qq++) {
                    int k = kb*32 + m*8 + qq*2;
                    float a0 = sB1[k], a1 = sB1[k+1];
                    #pragma unroll
                    for (int c = 0; c < 6; c++) {
                        a0 += f[c]*sW1[k*6+c];
                        a1 += f[c]*sW1[(k+1)*6+c];
                    }
                    __half2 hv = __floats2half2_rn(fmaxf(a0, 0.f), fmaxf(a1, 0.f));
                    pk[qq] = *(uint32_t*)&hv;
                }
                *(uint4*)(smc + SMS_HB + swz((uint32_t)(srow*128 + kb*64 + m*16))) =
                    make_uint4(pk[0], pk[1], pk[2], pk[3]);
            }
        }
        __syncthreads();
        // per-channel sums (fp16 -> fp32, register-resident across tiles)
        #pragma unroll 8
        for (int m = 0; m < 32; m++)
            sumacc += __half2float(*(__half*)(smc + SMS_HB +
                          swz((uint32_t)((sq*32 + m)*128 + sk*2))));
        // SYRK mma: 8 ksteps over 128 samples
        #pragma unroll
        for (int ks = 0; ks < 8; ks++) {
            uint32_t kbyt = (uint32_t)ks * 2048;
            uint32_t a[4];
            ldsm_x4_t(a, hbB + kbyt + a_sw);
            uint32_t bA[4], bB[4];
            ldsm_x4_t(bA, hbB + kbyt + b_sw0);
            ldsm_x4_t(bB, hbB + kbyt + b_sw1);
            uint32_t bb0[2] = {bA[0], bA[1]};
            uint32_t bb1[2] = {bA[2], bA[3]};
            uint32_t bb2[2] = {bB[0], bB[1]};
            uint32_t bb3[2] = {bB[2], bB[3]};
            mma16816(acc[0], a, bb0);
            mma16816(acc[1], a, bb1);
            mma16816(acc[2], a, bb2);
            mma16816(acc[3], a, bb3);
        }
        __syncthreads();
    }

    // flush accumulators
    #pragma unroll
    for (int j = 0; j < 4; j++) {
        int row = m0 + (lane >> 2), col = n0 + 8*j + (lane & 3)*2;
        atomicAdd(&g_M[row*64 + col],         acc[j][0]);
        atomicAdd(&g_M[row*64 + col + 1],     acc[j][1]);
        atomicAdd(&g_M[(row+8)*64 + col],     acc[j][2]);
        atomicAdd(&g_M[(row+8)*64 + col + 1], acc[j][3]);
    }
    atomicAdd(&g_h1sum[sk], sumacc);

    // ---- last-block BN2 tail ----
    __threadfence();
    __syncthreads();
    __shared__ unsigned amLast;
    if (t == 0) amLast = (atomicAdd(&g_cnt, 1u) == gridDim.x - 1u) ? 1u : 0u;
    __syncthreads();
    if (!amLast) return;

    if (t < 64) {
        #pragma unroll
        for (int c = 0; c < 6; c++) g_W1s[t*6+c] = sW1[t*6+c];
        g_b1s[t] = sB1[t];
    }
    __syncthreads();

    float* sM    = (float*)(smc + 4096);    // 4096 floats
    float* sW    = (float*)(smc + 20480);   // 4160 floats
    float* hm    = (float*)(smc + 37120);   // 64
    float* partm = (float*)(smc + 37376);   // 256
    float* partq = (float*)(smc + 38400);   // 256

    const float inv = 1.0f / (float)NSAMPLES;
    for (int i = t; i < 4096; i += 256) {
        sM[i] = __ldcg(&g_M[i]);
        sW[(i >> 6)*BW + (i & 63)] = W2[i];
    }
    if (t < 64) hm[t] = __ldcg(&g_h1sum[t]) * inv;
    __syncthreads();

    int o = t & 63, qq = t >> 6;
    const float* wv = &sW[o*BW];
    float lm = 0.f, lq = 0.f;
    for (int k = qq*16; k < qq*16 + 16; k++) {
        float wk = wv[k];
        lm += wk*hm[k];
        float s = 0.f;
        #pragma unroll 8
        for (int k2 = 0; k2 < 64; k2++) s += sM[k*64 + k2]*wv[k2];
        lq += wk*s;
    }
    partm[t] = lm; partq[t] = lq;
    __syncthreads();
    if (t < 64) {
        float m  = partm[t] + partm[t+64] + partm[t+128] + partm[t+192];
        float qv = (partq[t] + partq[t+64] + partq[t+128] + partq[t+192]) * inv;
        float var = fmaxf(qv - m*m, 0.f);
        float sc = g2[t]*rsqrtf(var + BNEPS);
        g_sc2[t] = sc; g_sh2[t] = b2[t] - m*sc;
    }
}

// ---------------- K3: HMMA fused layer (R11-proven, frozen) ------------------
#define SM_W2H 4096
#define SM_W3H 12288
#define SM_HB  28672
#define SM_RMX 45056
#define SM_RMN 49152
#define SM_MMA_TOTAL 53248

__global__ __launch_bounds__(256, 2) void k_mma(const float* __restrict__ W2,
                                                const float* __restrict__ W3) {
    extern __shared__ char smc[];
    float* smf = (float*)smc;
    uint32_t sbase = smem_to_u32(smc);
    int t = threadIdx.x, w = t >> 5, lane = t & 31;

    float* sW1  = smf;
    float* sB1  = smf + 384;
    float* sc2s = smf + 448;
    float* sh2s = smf + 512;
    float* csum = smf + 576;
    float* csq  = smf + 704;
    float* rmax = (float*)(smc + SM_RMX);
    float* rmin = (float*)(smc + SM_RMN);

    for (int i = t; i < 384; i += 256) sW1[i] = g_W1s[i];
    if (t < 64) { sB1[t] = g_b1s[t]; sc2s[t] = g_sc2[t]; sh2s[t] = g_sh2[t]; }
    if (t < 128){ csum[t] = 0.f; csq[t] = 0.f; }
    for (int i = t; i < 2048; i += 256) {
        int o = i >> 5, kk = (i & 31)*2;
        __half2 hv = __floats2half2_rn(W2[o*64 + kk], W2[o*64 + kk + 1]);
        *(uint32_t*)(smc + SM_W2H + swz((uint32_t)(o*128 + kk*2))) = *(uint32_t*)&hv;
    }
    for (int i = t; i < 4096; i += 256) {
        int o = i >> 5, kk = (i & 31)*2;
        __half2 hv = __floats2half2_rn(W3[o*64 + kk], W3[o*64 + kk + 1]);
        *(uint32_t*)(smc + SM_W3H + swz((uint32_t)(o*128 + kk*2))) = *(uint32_t*)&hv;
    }

    size_t s0 = (size_t)blockIdx.x * 128;

    {
        int srow = w*16 + (lane >> 1), kb = lane & 1;
        const float* fp = g_feat + (s0 + srow)*8;
        float4 f0 = *(const float4*)fp;
        float4 f1 = *(const float4*)(fp + 4);
        float f[6] = {f0.x, f0.y, f0.z, f0.w, f1.x, f1.y};
        #pragma unroll
        for (int m = 0; m < 4; m++) {
            uint32_t pk[4];
            #pragma unroll
            for (int q = 0; q < 4; q++) {
                int k = kb*32 + m*8 + q*2;
                float a0 = sB1[k], a1 = sB1[k+1];
                #pragma unroll
                for (int c = 0; c < 6; c++) {
                    a0 += f[c]*sW1[k*6+c];
                    a1 += f[c]*sW1[(k+1)*6+c];
                }
                __half2 hv = __floats2half2_rn(fmaxf(a0, 0.f), fmaxf(a1, 0.f));
                pk[q] = *(uint32_t*)&hv;
            }
            *(uint4*)(smc + SM_HB + swz((uint32_t)(srow*128 + kb*64 + m*16))) =
                make_uint4(pk[0], pk[1], pk[2], pk[3]);
        }
    }
    __syncthreads();

    int m0 = w*16;
    uint32_t hbB = sbase + SM_HB, w2B = sbase + SM_W2H, w3B = sbase + SM_W3H;
    int arow = m0 + (lane & 15);
    int acolb = ((lane >> 4) & 1) * 16;
    int ln = lane & 15;
    int brow = ln & 7;
    int bcolb = ((ln >> 3) & 1) * 16;

    float acc1[8][4];
    #pragma unroll
    for (int j = 0; j < 8; j++)
        #pragma unroll
        for (int i = 0; i < 4; i++) acc1[j][i] = 0.f;
    #pragma unroll
    for (int ks = 0; ks < 4; ks++) {
        int k0b = ks*32;
        uint32_t a[4];
        ldsm_x4(a, hbB + swz((uint32_t)(arow*128 + k0b + acolb)));
        #pragma unroll
        for (int j = 0; j < 8; j++) {
            uint32_t b[2];
            ldsm_x2(b, w2B + swz((uint32_t)((8*j + brow)*128 + k0b + bcolb)));
            mma16816(acc1[j], a, b);
        }
    }
    __syncwarp();
    {
        int r0 = m0 + (lane >> 2);
        #pragma unroll
        for (int j = 0; j < 8; j++) {
            int o = 8*j + 2*(lane & 3);
            float sc0 = sc2s[o], sh0 = sh2s[o], sc1 = sc2s[o+1], sh1 = sh2s[o+1];
            float y0 = fmaxf(acc1[j][0]*sc0 + sh0, 0.f);
            float y1 = fmaxf(acc1[j][1]*sc1 + sh1, 0.f);
            float y2 = fmaxf(acc1[j][2]*sc0 + sh0, 0.f);
            float y3 = fmaxf(acc1[j][3]*sc1 + sh1, 0.f);
            __half2 h01 = __floats2half2_rn(y0, y1);
            __half2 h23 = __floats2half2_rn(y2, y3);
            *(uint32_t*)(smc + SM_HB + swz((uint32_t)(r0*128 + o*2)))     = *(uint32_t*)&h01;
            *(uint32_t*)(smc + SM_HB + swz((uint32_t)((r0+8)*128 + o*2))) = *(uint32_t*)&h23;
        }
    }
    __syncwarp();

    float acc2[16][4];
    #pragma unroll
    for (int j = 0; j < 16; j++)
        #pragma unroll
        for (int i = 0; i < 4; i++) acc2[j][i] = 0.f;
    #pragma unroll
    for (int ks = 0; ks < 4; ks++) {
        int k0b = ks*32;
        uint32_t a[4];
        ldsm_x4(a, hbB + swz((uint32_t)(arow*128 + k0b + acolb)));
        #pragma unroll
        for (int j = 0; j < 16; j++) {
            uint32_t b[2];
            ldsm_x2(b, w3B + swz((uint32_t)((8*j + brow)*128 + k0b + bcolb)));
            mma16816(acc2[j], a, b);
        }
    }

    #pragma unroll
    for (int j = 0; j < 16; j++) {
        float d0 = acc2[j][0], d1 = acc2[j][1], d2 = acc2[j][2], d3 = acc2[j][3];
        float mx0 = fmaxf(d0, d2), mx1 = fmaxf(d1, d3);
        float mn0 = fminf(d0, d2), mn1 = fminf(d1, d3);
        float ps0 = d0 + d2, ps1 = d1 + d3;
        float pq0 = d0*d0 + d2*d2, pq1 = d1*d1 + d3*d3;
        #pragma unroll
        for (int off = 4; off < 32; off <<= 1) {
            mx0 = fmaxf(mx0, __shfl_xor_sync(0xffffffffu, mx0, off));
            mx1 = fmaxf(mx1, __shfl_xor_sync(0xffffffffu, mx1, off));
            mn0 = fminf(mn0, __shfl_xor_sync(0xffffffffu, mn0, off));
            mn1 = fminf(mn1, __shfl_xor_sync(0xffffffffu, mn1, off));
            ps0 += __shfl_xor_sync(0xffffffffu, ps0, off);
            ps1 += __shfl_xor_sync(0xffffffffu, ps1, off);
            pq0 += __shfl_xor_sync(0xffffffffu, pq0, off);
            pq1 += __shfl_xor_sync(0xffffffffu, pq1, off);
        }
        if (lane < 4) {
            int o = 8*j + 2*lane;
            rmax[w*128 + o]     = mx0;
            rmax[w*128 + o + 1] = mx1;
            rmin[w*128 + o]     = mn0;
            rmin[w*128 + o + 1] = mn1;
            atomicAdd(&csum[o],   ps0);
            atomicAdd(&csum[o+1], ps1);
            atomicAdd(&csq[o],    pq0);
            atomicAdd(&csq[o+1],  pq1);
        }
    }
    __syncthreads();

    for (int v = t; v < 512; v += 256) {
        int g = v >> 7, o = v & 127;
        float mx = fmaxf(rmax[(2*g)*128 + o], rmax[(2*g+1)*128 + o]);
        float mn = fminf(rmin[(2*g)*128 + o], rmin[(2*g+1)*128 + o]);
        g_gmax[(s0/32 + g)*128 + o] = mx;
        g_gmin[(s0/32 + g)*128 + o] = mn;
    }
    if (t < 128) { atomicAdd(&g_x3sum[t], csum[t]); atomicAdd(&g_x3sq[t], csq[t]); }
}

// ---------------- K4: bn3 (inline) + relu on group max/min, transposed out ----
__global__ void k_out2(const float* __restrict__ g3, const float* __restrict__ b3,
                       float* __restrict__ out2) {
    __shared__ float tr[32*129];
    __shared__ float ssc[128], ssh[128];
    int b = blockIdx.y;
    int s0 = blockIdx.x * 32;
    int t = threadIdx.x;
    if (t < 128) {
        const float inv = 1.0f / (float)NSAMPLES;
        float m = g_x3sum[t]*inv;
        float v = fmaxf(g_x3sq[t]*inv - m*m, 0.f);
        float sc = g3[t]*rsqrtf(v + BNEPS);
        ssc[t] = sc; ssh[t] = b3[t] - m*sc;
    }
    __syncthreads();
    for (int i = t; i < 32*128; i += 256) {
        int gi = i >> 7, o = i & 127;
        float sc = ssc[o], sh = ssh[o];
        size_t g = (size_t)(b*SS + s0 + gi);
        float v = (sc >= 0.f) ? g_gmax[g*128 + o] : g_gmin[g*128 + o];
        tr[gi*129 + o] = fmaxf(sc*v + sh, 0.f);
    }
    __syncthreads();
    for (int i = t; i < 32*128; i += 256) {
        int o = i >> 5, si = i & 31;
        out2[((size_t)(b*128 + o))*SS + s0 + si] = tr[si*129 + o];
    }
}

// ---------------- launch ----------------
extern "C" void kernel_launch(void* const* d_in, const int* in_sizes, int n_in,
                              void* d_out, int out_size) {
    const float* xyz    = (const float*)d_in[0];
    const float* points = (const float*)d_in[1];
    const int*   fps    = (const int*)  d_in[2];
    const float* W1 = (const float*)d_in[3];
    const float* g1 = (const float*)d_in[4];
    const float* b1 = (const float*)d_in[5];
    const float* W2 = (const float*)d_in[6];
    const float* g2 = (const float*)d_in[7];
    const float* b2 = (const float*)d_in[8];
    const float* W3 = (const float*)d_in[9];
    const float* g3 = (const float*)d_in[10];
    const float* b3 = (const float*)d_in[11];

    float* out1 = (float*)d_out;
    float* out2 = (float*)d_out + (size_t)BB*3*SS;

    const int SMEM_BALL  = (3*NN)*4 + 8*32*4;
    const int SMEM_STATS = 39424;

    cudaFuncSetAttribute(k_ball,  cudaFuncAttributeMaxDynamicSharedMemorySize, SMEM_BALL);
    cudaFuncSetAttribute(k_stats, cudaFuncAttributeMaxDynamicSharedMemorySize, SMEM_STATS);
    cudaFuncSetAttribute(k_mma,   cudaFuncAttributeMaxDynamicSharedMemorySize, SM_MMA_TOTAL);

    k_zero<<<1, 256>>>();
    k_ball<<<dim3(SS/32, BB), 256, SMEM_BALL>>>(xyz, points, fps, out1);
    k_stats<<<592, 256, SMEM_STATS>>>(W1, g1, b1, W2, g2, b2);
    k_mma<<<NTILES, 256, SM_MMA_TOTAL>>>(W2, W3);
    k_out2<<<dim3(SS/32, BB), 256>>>(g3, b3, out2);
}

// round 13
// speedup vs baseline: 1.2448x; 1.2448x over previous
#include <cuda_runtime.h>
#include <cuda_fp16.h>
#include <math.h>
#include <stdint.h>

#define BB 8
#define NN 8192
#define SS 2048
#define NSAMP 32
#define NSAMPLES (BB*SS*NSAMP)   /* 524288 */
#define NGROUPS (BB*SS)          /* 16384  */
#define NTILES (NSAMPLES/128)    /* 4096   */
#define R2 0.04f
#define BNEPS 1e-5f

typedef unsigned long long ull;

// ---------------- device scratch ----------------
__device__ float g_feat[(size_t)NSAMPLES*8];
__device__ float g_gmax[(size_t)NGROUPS*128];
__device__ float g_gmin[(size_t)NGROUPS*128];
__device__ float g_fsum[6];
__device__ float g_fmom[21];
__device__ float g_M[64*64];
__device__ float g_h1sum[64];
__device__ float g_x3sum[128], g_x3sq[128];
__device__ float g_W1s[64*6], g_b1s[64];
__device__ float g_sc2[64], g_sh2[64];
__device__ unsigned g_cnt;

// ---------------- f32x2 helpers (k_stats) ----------------
static __device__ __forceinline__ void fma2(ull& d, ull a, ull b) {
    asm("fma.rn.f32x2 %0, %1, %2, %0;" : "+l"(d) : "l"(a), "l"(b));
}
static __device__ __forceinline__ float hadd2(ull v) {
    float lo, hi;
    asm("mov.b64 {%0,%1}, %2;" : "=f"(lo), "=f"(hi) : "l"(v));
    return lo + hi;
}

// ---------------- mma.sync helpers ----------------
static __device__ __forceinline__ uint32_t smem_to_u32(const void* p) {
    uint32_t a;
    asm("{ .reg .u64 tmp; cvta.to.shared.u64 tmp, %1; cvt.u32.u64 %0, tmp; }"
        : "=r"(a) : "l"(p));
    return a;
}
static __device__ __forceinline__ uint32_t swz(uint32_t off) {
    return off ^ ((off >> 3) & 0x70);
}
static __device__ __forceinline__ void ldsm_x4(uint32_t (&a)[4], uint32_t addr) {
    asm volatile("ldmatrix.sync.aligned.m8n8.x4.shared.b16 {%0,%1,%2,%3}, [%4];"
        : "=r"(a[0]), "=r"(a[1]), "=r"(a[2]), "=r"(a[3]) : "r"(addr));
}
static __device__ __forceinline__ void mma16816(float (&d)[4], const uint32_t (&a)[4],
                                                const uint32_t (&b)[2]) {
    asm volatile("mma.sync.aligned.m16n8k16.row.col.f32.f16.f16.f32 "
        "{%0,%1,%2,%3}, {%4,%5,%6,%7}, {%8,%9}, {%0,%1,%2,%3};"
        : "+f"(d[0]), "+f"(d[1]), "+f"(d[2]), "+f"(d[3])
        : "r"(a[0]), "r"(a[1]), "r"(a[2]), "r"(a[3]), "r"(b[0]), "r"(b[1]));
}

// ---------------- K0: zero accumulators ----------------
__global__ void k_zero() {
    int t = threadIdx.x;
    for (int i = t; i < 4096; i += 256) g_M[i] = 0.f;
    if (t < 6)  g_fsum[t] = 0.f;
    if (t < 21) g_fmom[t] = 0.f;
    if (t < 64) g_h1sum[t] = 0.f;
    if (t < 128){ g_x3sum[t] = 0.f; g_x3sq[t] = 0.f; }
    if (t == 0) g_cnt = 0u;
}

// ---------------- K1: ball query + feat + feat moments + out1 ----------------
__global__ __launch_bounds__(256) void k_ball(const float* __restrict__ xyz,
                                              const float* __restrict__ points,
                                              const int*   __restrict__ fps,
                                              float* __restrict__ out1) {
    extern __shared__ float sm[];
    float* sx = sm;
    float* sy = sm + NN;
    float* sz = sm + 2*NN;
    int*   fnd = (int*)(sm + 3*NN);

    int b = blockIdx.y;
    int qbase = blockIdx.x * 32;
    int tid = threadIdx.x;

    for (int i = tid; i < NN; i += 256) {
        sx[i] = xyz[(b*3+0)*NN + i];
        sy[i] = xyz[(b*3+1)*NN + i];
        sz[i] = xyz[(b*3+2)*NN + i];
    }
    __syncthreads();

    int w = tid >> 5, lane = tid & 31;
    int* f = fnd + w*32;
    unsigned lmask = (1u << lane) - 1u;

    float s1[6], s2[21];
    #pragma unroll
    for (int i = 0; i < 6; i++)  s1[i] = 0.f;
    #pragma unroll
    for (int i = 0; i < 21; i++) s2[i] = 0.f;

    for (int qi = 0; qi < 4; qi++) {
        int s = qbase + w*4 + qi;
        int cidx = fps[b*SS + s];
        float cx = sx[cidx], cy = sy[cidx], cz = sz[cidx];
        if (lane == 0) {
            out1[(b*3+0)*SS + s] = cx;
            out1[(b*3+1)*SS + s] = cy;
            out1[(b*3+2)*SS + s] = cz;
        }
        int cnt = 0;
        for (int chunk = 0; chunk < NN/32; chunk++) {
            int j = chunk*32 + lane;
            float dx = __fsub_rn(sx[j], cx);
            float dy = __fsub_rn(sy[j], cy);
            float dz = __fsub_rn(sz[j], cz);
            float d2 = __fadd_rn(__fadd_rn(__fmul_rn(dx,dx), __fmul_rn(dy,dy)),
                                 __fmul_rn(dz,dz));
            bool hit = (d2 <= R2);
            unsigned mask = __ballot_sync(0xffffffffu, hit);
            if (hit) {
                int pos = cnt + __popc(mask & lmask);
                if (pos < 32) f[pos] = j;
            }
            cnt += __popc(mask);
            if (cnt >= 32) break;
        }
        __syncwarp();
        int j = (lane < cnt) ? f[lane] : f[0];
        __syncwarp();

        float fx = sx[j]-cx, fy = sy[j]-cy, fz = sz[j]-cz;
        float p0 = points[(b*3+0)*NN + j];
        float p1 = points[(b*3+1)*NN + j];
        float p2 = points[(b*3+2)*NN + j];

        size_t base = ((size_t)(b*SS + s)*NSAMP + lane) * 8;
        *(float4*)(g_feat + base)     = make_float4(fx, fy, fz, p0);
        *(float4*)(g_feat + base + 4) = make_float4(p1, p2, 0.f, 0.f);

        float fv[6] = {fx, fy, fz, p0, p1, p2};
        int k = 0;
        #pragma unroll
        for (int c = 0; c < 6; c++) {
            s1[c] += fv[c];
            #pragma unroll
            for (int c2 = 0; c2 <= c; c2++) s2[k++] += fv[c]*fv[c2];
        }
    }

    __shared__ float red[27];
    if (tid < 27) red[tid] = 0.f;
    __syncthreads();
    #pragma unroll
    for (int i = 0; i < 6; i++) {
        float v = s1[i];
        for (int off = 16; off; off >>= 1) v += __shfl_down_sync(0xffffffffu, v, off);
        if (lane == 0) atomicAdd(&red[i], v);
    }
    #pragma unroll
    for (int i = 0; i < 21; i++) {
        float v = s2[i];
        for (int off = 16; off; off >>= 1) v += __shfl_down_sync(0xffffffffu, v, off);
        if (lane == 0) atomicAdd(&red[6+i], v);
    }
    __syncthreads();
    if (tid < 6)       atomicAdd(&g_fsum[tid], red[tid]);
    else if (tid < 27) atomicAdd(&g_fmom[tid-6], red[tid]);
}

// ---------------- BN1 fold helper ----------------
static __device__ __forceinline__ void bn1_fold_block(
        const float* __restrict__ W1, const float* __restrict__ g1,
        const float* __restrict__ b1, float* sW1, float* sB1,
        float* sMu, float* sC, int t) {
    if (t == 0) {
        const float inv = 1.0f / (float)NSAMPLES;
        for (int c = 0; c < 6; c++) sMu[c] = g_fsum[c]*inv;
        int k = 0;
        for (int c = 0; c < 6; c++)
            for (int c2 = 0; c2 <= c; c2++) {
                float v = g_fmom[k++]*inv; sC[c*6+c2] = v; sC[c2*6+c] = v;
            }
    }
    __syncthreads();
    if (t < 64) {
        float w[6];
        #pragma unroll
        for (int c = 0; c < 6; c++) w[c] = W1[t*6+c];
        float mean = 0.f;
        #pragma unroll
        for (int c = 0; c < 6; c++) mean += w[c]*sMu[c];
        float e2 = 0.f;
        #pragma unroll
        for (int c = 0; c < 6; c++) {
            float tt = 0.f;
            #pragma unroll
            for (int c2 = 0; c2 < 6; c2++) tt += sC[c*6+c2]*w[c2];
            e2 += w[c]*tt;
        }
        float var = fmaxf(e2 - mean*mean, 0.f);
        float sc = g1[t]*rsqrtf(var + BNEPS);
        #pragma unroll
        for (int c = 0; c < 6; c++) sW1[t*6+c] = w[c]*sc;
        sB1[t] = b1[t] - mean*sc;
    }
    __syncthreads();
}

// ---------------- K2: stats — h1 mean + f32x2 SYRK (R8-proven); BN2 tail ----
#define P1PAD 134
#define BW 65
__global__ __launch_bounds__(256) void k_stats(const float* __restrict__ W1,
                                               const float* __restrict__ g1,
                                               const float* __restrict__ b1,
                                               const float* __restrict__ W2,
                                               const float* __restrict__ g2,
                                               const float* __restrict__ b2) {
    extern __shared__ float sm[];
    float* sW1  = sm;
    float* sB1  = sm + 384;
    float* ssum = sm + 448;
    float* sMu  = sm + 512;
    float* sC   = sm + 518;
    float* sH   = sm + 560;

    int t = threadIdx.x;
    if (t < 64) ssum[t] = 0.f;
    bn1_fold_block(W1, g1, b1, sW1, sB1, sMu, sC, t);

    int to = t & 15, ts = t >> 4;
    ull accM[16];
    #pragma unroll
    for (int i = 0; i < 16; i++) accM[i] = 0ull;

    const ull* ra[4]; const ull* rb[4];
    #pragma unroll
    for (int i = 0; i < 4; i++) ra[i] = (const ull*)&sH[(ts + 16*i)*P1PAD];
    #pragma unroll
    for (int j = 0; j < 4; j++) rb[j] = (const ull*)&sH[(to + 16*j)*P1PAD];

    for (int tile = blockIdx.x; tile < NTILES; tile += gridDim.x) {
        size_t s0 = (size_t)tile * 128;
        {
            int s = t & 127, kb = t >> 7;
            const float* fp = g_feat + (s0 + s)*8;
            float4 f0 = *(const float4*)fp;
            float4 f1 = *(const float4*)(fp + 4);
            float f[6] = {f0.x, f0.y, f0.z, f0.w, f1.x, f1.y};
            #pragma unroll 8
            for (int kk = 0; kk < 32; kk++) {
                int k = kb*32 + kk;
                float a = sB1[k];
                #pragma unroll
                for (int c = 0; c < 6; c++) a += f[c]*sW1[k*6+c];
                sH[k*P1PAD + s] = fmaxf(a, 0.f);
            }
        }
        __syncthreads();
        {
            int k = t & 63, q = t >> 6;
            float local = 0.f;
            #pragma unroll 8
            for (int m = 0; m < 32; m++) local += sH[k*P1PAD + q*32 + m];
            atomicAdd(&ssum[k], local);
        }
        #pragma unroll 2
        for (int s2 = 0; s2 < 64; s2++) {
            ull ha[4], hb[4];
            #pragma unroll
            for (int i = 0; i < 4; i++) ha[i] = ra[i][s2];
            #pragma unroll
            for (int j = 0; j < 4; j++) hb[j] = rb[j][s2];
            #pragma unroll
            for (int i = 0; i < 4; i++)
                #pragma unroll
                for (int j = 0; j < 4; j++) fma2(accM[i*4+j], ha[i], hb[j]);
        }
        __syncthreads();
    }

    #pragma unroll
    for (int i = 0; i < 4; i++)
        #pragma unroll
        for (int j = 0; j < 4; j++)
            atomicAdd(&g_M[(ts + 16*i)*64 + (to + 16*j)], hadd2(accM[i*4+j]));
    __syncthreads();
    if (t < 64) atomicAdd(&g_h1sum[t], ssum[t]);

    // ---- last-block BN2 tail ----
    __threadfence();
    __syncthreads();
    __shared__ unsigned amLast;
    if (t == 0) amLast = (atomicAdd(&g_cnt, 1u) == gridDim.x - 1u) ? 1u : 0u;
    __syncthreads();
    if (!amLast) return;

    if (t < 64) {
        #pragma unroll
        for (int c = 0; c < 6; c++) g_W1s[t*6+c] = sW1[t*6+c];
        g_b1s[t] = sB1[t];
    }
    __syncthreads();

    float* sM    = sH;
    float* sW    = sH + 4096;
    float* hm    = sH + 8256;
    float* partm = sm;
    float* partq = sm + 256;

    const float inv = 1.0f / (float)NSAMPLES;
    for (int i = t; i < 4096; i += 256) {
        sM[i] = __ldcg(&g_M[i]);
        sW[(i >> 6)*BW + (i & 63)] = W2[i];
    }
    if (t < 64) hm[t] = __ldcg(&g_h1sum[t]) * inv;
    __syncthreads();

    int o = t & 63, q = t >> 6;
    const float* w = &sW[o*BW];
    float lm = 0.f, lq = 0.f;
    for (int k = q*16; k < q*16 + 16; k++) {
        float wk = w[k];
        lm += wk*hm[k];
        float s = 0.f;
        #pragma unroll 8
        for (int k2 = 0; k2 < 64; k2++) s += sM[k*64 + k2]*w[k2];
        lq += wk*s;
    }
    partm[t] = lm; partq[t] = lq;
    __syncthreads();
    if (t < 64) {
        float m  = partm[t] + partm[t+64] + partm[t+128] + partm[t+192];
        float qv = (partq[t] + partq[t+64] + partq[t+128] + partq[t+192]) * inv;
        float var = fmaxf(qv - m*m, 0.f);
        float sc = g2[t]*rsqrtf(var + BNEPS);
        g_sc2[t] = sc; g_sh2[t] = b2[t] - m*sc;
    }
}

// ---------------- K3: HMMA fused layer — ldsm_x4 B loads (2 n-tiles/load) ----
#define SM_W2H 4096
#define SM_W3H 12288
#define SM_HB  28672
#define SM_RMX 45056
#define SM_RMN 49152
#define SM_MMA_TOTAL 53248

__global__ __launch_bounds__(256, 2) void k_mma(const float* __restrict__ W2,
                                                const float* __restrict__ W3) {
    extern __shared__ char smc[];
    float* smf = (float*)smc;
    uint32_t sbase = smem_to_u32(smc);
    int t = threadIdx.x, w = t >> 5, lane = t & 31;

    float* sW1  = smf;
    float* sB1  = smf + 384;
    float* sc2s = smf + 448;
    float* sh2s = smf + 512;
    float* csum = smf + 576;
    float* csq  = smf + 704;
    float* rmax = (float*)(smc + SM_RMX);
    float* rmin = (float*)(smc + SM_RMN);

    for (int i = t; i < 384; i += 256) sW1[i] = g_W1s[i];
    if (t < 64) { sB1[t] = g_b1s[t]; sc2s[t] = g_sc2[t]; sh2s[t] = g_sh2[t]; }
    if (t < 128){ csum[t] = 0.f; csq[t] = 0.f; }
    for (int i = t; i < 2048; i += 256) {
        int o = i >> 5, kk = (i & 31)*2;
        __half2 hv = __floats2half2_rn(W2[o*64 + kk], W2[o*64 + kk + 1]);
        *(uint32_t*)(smc + SM_W2H + swz((uint32_t)(o*128 + kk*2))) = *(uint32_t*)&hv;
    }
    for (int i = t; i < 4096; i += 256) {
        int o = i >> 5, kk = (i & 31)*2;
        __half2 hv = __floats2half2_rn(W3[o*64 + kk], W3[o*64 + kk + 1]);
        *(uint32_t*)(smc + SM_W3H + swz((uint32_t)(o*128 + kk*2))) = *(uint32_t*)&hv;
    }

    size_t s0 = (size_t)blockIdx.x * 128;

    // step A: h1 fp32 -> fp16 swizzled; 2 threads per sample
    {
        int srow = w*16 + (lane >> 1), kb = lane & 1;
        const float* fp = g_feat + (s0 + srow)*8;
        float4 f0 = *(const float4*)fp;
        float4 f1 = *(const float4*)(fp + 4);
        float f[6] = {f0.x, f0.y, f0.z, f0.w, f1.x, f1.y};
        #pragma unroll
        for (int m = 0; m < 4; m++) {
            uint32_t pk[4];
            #pragma unroll
            for (int q = 0; q < 4; q++) {
                int k = kb*32 + m*8 + q*2;
                float a0 = sB1[k], a1 = sB1[k+1];
                #pragma unroll
                for (int c = 0; c < 6; c++) {
                    a0 += f[c]*sW1[k*6+c];
                    a1 += f[c]*sW1[(k+1)*6+c];
                }
                __half2 hv = __floats2half2_rn(fmaxf(a0, 0.f), fmaxf(a1, 0.f));
                pk[q] = *(uint32_t*)&hv;
            }
            *(uint4*)(smc + SM_HB + swz((uint32_t)(srow*128 + kb*64 + m*16))) =
                make_uint4(pk[0], pk[1], pk[2], pk[3]);
        }
    }
    __syncthreads();

    int m0 = w*16;
    uint32_t hbB = sbase + SM_HB, w2B = sbase + SM_W2H, w3B = sbase + SM_W3H;
    int arow = m0 + (lane & 15);
    int acolb = ((lane >> 4) & 1) * 16;
    // x4 B-load lane mapping: 2 n-tiles per load
    int b4row = ((lane >> 4) << 3) + (lane & 7);     // + tile-pair base*16
    int b4colb = ((lane >> 3) & 1) * 16;             // + k-step base

    // GEMM1: 8 n-tiles via 4 x4-loads
    float acc1[8][4];
    #pragma unroll
    for (int j = 0; j < 8; j++)
        #pragma unroll
        for (int i = 0; i < 4; i++) acc1[j][i] = 0.f;
    #pragma unroll
    for (int ks = 0; ks < 4; ks++) {
        int k0b = ks*32;
        uint32_t a[4];
        ldsm_x4(a, hbB + swz((uint32_t)(arow*128 + k0b + acolb)));
        #pragma unroll
        for (int u = 0; u < 4; u++) {
            uint32_t b4[4];
            ldsm_x4(b4, w2B + swz((uint32_t)((u*16 + b4row)*128 + k0b + b4colb)));
            uint32_t b0[2] = {b4[0], b4[1]};
            uint32_t b1[2] = {b4[2], b4[3]};
            mma16816(acc1[2*u],   a, b0);
            mma16816(acc1[2*u+1], a, b1);
        }
    }
    __syncwarp();
    // epilogue1: bn2+relu -> fp16 h2 into own rows
    {
        int r0 = m0 + (lane >> 2);
        #pragma unroll
        for (int j = 0; j < 8; j++) {
            int o = 8*j + 2*(lane & 3);
            float sc0 = sc2s[o], sh0 = sh2s[o], sc1 = sc2s[o+1], sh1 = sh2s[o+1];
            float y0 = fmaxf(acc1[j][0]*sc0 + sh0, 0.f);
            float y1 = fmaxf(acc1[j][1]*sc1 + sh1, 0.f);
            float y2 = fmaxf(acc1[j][2]*sc0 + sh0, 0.f);
            float y3 = fmaxf(acc1[j][3]*sc1 + sh1, 0.f);
            __half2 h01 = __floats2half2_rn(y0, y1);
            __half2 h23 = __floats2half2_rn(y2, y3);
            *(uint32_t*)(smc + SM_HB + swz((uint32_t)(r0*128 + o*2)))     = *(uint32_t*)&h01;
            *(uint32_t*)(smc + SM_HB + swz((uint32_t)((r0+8)*128 + o*2))) = *(uint32_t*)&h23;
        }
    }
    __syncwarp();

    // GEMM2: 16 n-tiles via 8 x4-loads
    float acc2[16][4];
    #pragma unroll
    for (int j = 0; j < 16; j++)
        #pragma unroll
        for (int i = 0; i < 4; i++) acc2[j][i] = 0.f;
    #pragma unroll
    for (int ks = 0; ks < 4; ks++) {
        int k0b = ks*32;
        uint32_t a[4];
        ldsm_x4(a, hbB + swz((uint32_t)(arow*128 + k0b + acolb)));
        #pragma unroll
        for (int u = 0; u < 8; u++) {
            uint32_t b4[4];
            ldsm_x4(b4, w3B + swz((uint32_t)((u*16 + b4row)*128 + k0b + b4colb)));
            uint32_t b0[2] = {b4[0], b4[1]};
            uint32_t b1[2] = {b4[2], b4[3]};
            mma16816(acc2[2*u],   a, b0);
            mma16816(acc2[2*u+1], a, b1);
        }
    }

    // epilogue2: butterfly reduce -> group max/min + stats
    #pragma unroll
    for (int j = 0; j < 16; j++) {
        float d0 = acc2[j][0], d1 = acc2[j][1], d2 = acc2[j][2], d3 = acc2[j][3];
        float mx0 = fmaxf(d0, d2), mx1 = fmaxf(d1, d3);
        float mn0 = fminf(d0, d2), mn1 = fminf(d1, d3);
        float ps0 = d0 + d2, ps1 = d1 + d3;
        float pq0 = d0*d0 + d2*d2, pq1 = d1*d1 + d3*d3;
        #pragma unroll
        for (int off = 4; off < 32; off <<= 1) {
            mx0 = fmaxf(mx0, __shfl_xor_sync(0xffffffffu, mx0, off));
            mx1 = fmaxf(mx1, __shfl_xor_sync(0xffffffffu, mx1, off));
            mn0 = fminf(mn0, __shfl_xor_sync(0xffffffffu, mn0, off));
            mn1 = fminf(mn1, __shfl_xor_sync(0xffffffffu, mn1, off));
            ps0 += __shfl_xor_sync(0xffffffffu, ps0, off);
            ps1 += __shfl_xor_sync(0xffffffffu, ps1, off);
            pq0 += __shfl_xor_sync(0xffffffffu, pq0, off);
            pq1 += __shfl_xor_sync(0xffffffffu, pq1, off);
        }
        if (lane < 4) {
            int o = 8*j + 2*lane;
            rmax[w*128 + o]     = mx0;
            rmax[w*128 + o + 1] = mx1;
            rmin[w*128 + o]     = mn0;
            rmin[w*128 + o + 1] = mn1;
            atomicAdd(&csum[o],   ps0);
            atomicAdd(&csum[o+1], ps1);
            atomicAdd(&csq[o],    pq0);
            atomicAdd(&csq[o+1],  pq1);
        }
    }
    __syncthreads();

    for (int v = t; v < 512; v += 256) {
        int g = v >> 7, o = v & 127;
        float mx = fmaxf(rmax[(2*g)*128 + o], rmax[(2*g+1)*128 + o]);
        float mn = fminf(rmin[(2*g)*128 + o], rmin[(2*g+1)*128 + o]);
        g_gmax[(s0/32 + g)*128 + o] = mx;
        g_gmin[(s0/32 + g)*128 + o] = mn;
    }
    if (t < 128) { atomicAdd(&g_x3sum[t], csum[t]); atomicAdd(&g_x3sq[t], csq[t]); }
}

// ---------------- K4: bn3 (inline) + relu on group max/min, transposed out ----
__global__ void k_out2(const float* __restrict__ g3, const float* __restrict__ b3,
                       float* __restrict__ out2) {
    __shared__ float tr[32*129];
    __shared__ float ssc[128], ssh[128];
    int b = blockIdx.y;
    int s0 = blockIdx.x * 32;
    int t = threadIdx.x;
    if (t < 128) {
        const float inv = 1.0f / (float)NSAMPLES;
        float m = g_x3sum[t]*inv;
        float v = fmaxf(g_x3sq[t]*inv - m*m, 0.f);
        float sc = g3[t]*rsqrtf(v + BNEPS);
        ssc[t] = sc; ssh[t] = b3[t] - m*sc;
    }
    __syncthreads();
    for (int i = t; i < 32*128; i += 256) {
        int gi = i >> 7, o = i & 127;
        float sc = ssc[o], sh = ssh[o];
        size_t g = (size_t)(b*SS + s0 + gi);
        float v = (sc >= 0.f) ? g_gmax[g*128 + o] : g_gmin[g*128 + o];
        tr[gi*129 + o] = fmaxf(sc*v + sh, 0.f);
    }
    __syncthreads();
    for (int i = t; i < 32*128; i += 256) {
        int o = i >> 5, si = i & 31;
        out2[((size_t)(b*128 + o))*SS + s0 + si] = tr[si*129 + o];
    }
}

// ---------------- launch ----------------
extern "C" void kernel_launch(void* const* d_in, const int* in_sizes, int n_in,
                              void* d_out, int out_size) {
    const float* xyz    = (const float*)d_in[0];
    const float* points = (const float*)d_in[1];
    const int*   fps    = (const int*)  d_in[2];
    const float* W1 = (const float*)d_in[3];
    const float* g1 = (const float*)d_in[4];
    const float* b1 = (const float*)d_in[5];
    const float* W2 = (const float*)d_in[6];
    const float* g2 = (const float*)d_in[7];
    const float* b2 = (const float*)d_in[8];
    const float* W3 = (const float*)d_in[9];
    const float* g3 = (const float*)d_in[10];
    const float* b3 = (const float*)d_in[11];

    float* out1 = (float*)d_out;
    float* out2 = (float*)d_out + (size_t)BB*3*SS;

    const int SMEM_BALL  = (3*NN)*4 + 8*32*4;
    const int SMEM_STATS = (560 + 64*P1PAD)*4;

    cudaFuncSetAttribute(k_ball,  cudaFuncAttributeMaxDynamicSharedMemorySize, SMEM_BALL);
    cudaFuncSetAttribute(k_stats, cudaFuncAttributeMaxDynamicSharedMemorySize, SMEM_STATS);
    cudaFuncSetAttribute(k_mma,   cudaFuncAttributeMaxDynamicSharedMemorySize, SM_MMA_TOTAL);

    k_zero<<<1, 256>>>();
    k_ball<<<dim3(SS/32, BB), 256, SMEM_BALL>>>(xyz, points, fps, out1);
    k_stats<<<592, 256, SMEM_STATS>>>(W1, g1, b1, W2, g2, b2);
    k_mma<<<NTILES, 256, SM_MMA_TOTAL>>>(W2, W3);
    k_out2<<<dim3(SS/32, BB), 256>>>(g3, b3, out2);
}

// round 14
// speedup vs baseline: 1.2950x; 1.0404x over previous
#include <cuda_runtime.h>
#include <cuda_fp16.h>
#include <math.h>
#include <stdint.h>

#define BB 8
#define NN 8192
#define SS 2048
#define NSAMP 32
#define NSAMPLES (BB*SS*NSAMP)   /* 524288 */
#define NGROUPS (BB*SS)          /* 16384  */
#define NTILES (NSAMPLES/128)    /* 4096   */
#define R2 0.04f
#define BNEPS 1e-5f

typedef unsigned long long ull;

// ---------------- device scratch ----------------
__device__ float g_feat[(size_t)NSAMPLES*8];
__device__ float g_gmax[(size_t)NGROUPS*128];
__device__ float g_gmin[(size_t)NGROUPS*128];
__device__ float g_fsum[6];
__device__ float g_fmom[21];
__device__ float g_M[64*64];
__device__ float g_h1sum[64];
__device__ float g_x3sum[128], g_x3sq[128];
__device__ float g_W1s[64*6], g_b1s[64];
__device__ float g_sc2[64], g_sh2[64];
__device__ unsigned g_cnt;

// ---------------- f32x2 helpers (k_stats) ----------------
static __device__ __forceinline__ void fma2(ull& d, ull a, ull b) {
    asm("fma.rn.f32x2 %0, %1, %2, %0;" : "+l"(d) : "l"(a), "l"(b));
}
static __device__ __forceinline__ float hadd2(ull v) {
    float lo, hi;
    asm("mov.b64 {%0,%1}, %2;" : "=f"(lo), "=f"(hi) : "l"(v));
    return lo + hi;
}

// ---------------- mma.sync helpers ----------------
static __device__ __forceinline__ uint32_t smem_to_u32(const void* p) {
    uint32_t a;
    asm("{ .reg .u64 tmp; cvta.to.shared.u64 tmp, %1; cvt.u32.u64 %0, tmp; }"
        : "=r"(a) : "l"(p));
    return a;
}
static __device__ __forceinline__ uint32_t swz(uint32_t off) {
    return off ^ ((off >> 3) & 0x70);
}
static __device__ __forceinline__ void ldsm_x4(uint32_t (&a)[4], uint32_t addr) {
    asm volatile("ldmatrix.sync.aligned.m8n8.x4.shared.b16 {%0,%1,%2,%3}, [%4];"
        : "=r"(a[0]), "=r"(a[1]), "=r"(a[2]), "=r"(a[3]) : "r"(addr));
}
static __device__ __forceinline__ void mma16816(float (&d)[4], const uint32_t (&a)[4],
                                                const uint32_t (&b)[2]) {
    asm volatile("mma.sync.aligned.m16n8k16.row.col.f32.f16.f16.f32 "
        "{%0,%1,%2,%3}, {%4,%5,%6,%7}, {%8,%9}, {%0,%1,%2,%3};"
        : "+f"(d[0]), "+f"(d[1]), "+f"(d[2]), "+f"(d[3])
        : "r"(a[0]), "r"(a[1]), "r"(a[2]), "r"(a[3]), "r"(b[0]), "r"(b[1]));
}

// ---------------- K0: zero accumulators ----------------
__global__ void k_zero() {
    int t = threadIdx.x;
    for (int i = t; i < 4096; i += 256) g_M[i] = 0.f;
    if (t < 6)  g_fsum[t] = 0.f;
    if (t < 21) g_fmom[t] = 0.f;
    if (t < 64) g_h1sum[t] = 0.f;
    if (t < 128){ g_x3sum[t] = 0.f; g_x3sq[t] = 0.f; }
    if (t == 0) g_cnt = 0u;
}

// ---------------- K1: ball query + feat + feat moments + out1 ----------------
__global__ __launch_bounds__(256) void k_ball(const float* __restrict__ xyz,
                                              const float* __restrict__ points,
                                              const int*   __restrict__ fps,
                                              float* __restrict__ out1) {
    extern __shared__ float sm[];
    float* sx = sm;
    float* sy = sm + NN;
    float* sz = sm + 2*NN;
    int*   fnd = (int*)(sm + 3*NN);

    int b = blockIdx.y;
    int qbase = blockIdx.x * 32;
    int tid = threadIdx.x;

    for (int i = tid; i < NN; i += 256) {
        sx[i] = xyz[(b*3+0)*NN + i];
        sy[i] = xyz[(b*3+1)*NN + i];
        sz[i] = xyz[(b*3+2)*NN + i];
    }
    __syncthreads();

    int w = tid >> 5, lane = tid & 31;
    int* f = fnd + w*32;
    unsigned lmask = (1u << lane) - 1u;

    float s1[6], s2[21];
    #pragma unroll
    for (int i = 0; i < 6; i++)  s1[i] = 0.f;
    #pragma unroll
    for (int i = 0; i < 21; i++) s2[i] = 0.f;

    for (int qi = 0; qi < 4; qi++) {
        int s = qbase + w*4 + qi;
        int cidx = fps[b*SS + s];
        float cx = sx[cidx], cy = sy[cidx], cz = sz[cidx];
        if (lane == 0) {
            out1[(b*3+0)*SS + s] = cx;
            out1[(b*3+1)*SS + s] = cy;
            out1[(b*3+2)*SS + s] = cz;
        }
        int cnt = 0;
        for (int chunk = 0; chunk < NN/32; chunk++) {
            int j = chunk*32 + lane;
            float dx = __fsub_rn(sx[j], cx);
            float dy = __fsub_rn(sy[j], cy);
            float dz = __fsub_rn(sz[j], cz);
            float d2 = __fadd_rn(__fadd_rn(__fmul_rn(dx,dx), __fmul_rn(dy,dy)),
                                 __fmul_rn(dz,dz));
            bool hit = (d2 <= R2);
            unsigned mask = __ballot_sync(0xffffffffu, hit);
            if (hit) {
                int pos = cnt + __popc(mask & lmask);
                if (pos < 32) f[pos] = j;
            }
            cnt += __popc(mask);
            if (cnt >= 32) break;
        }
        __syncwarp();
        int j = (lane < cnt) ? f[lane] : f[0];
        __syncwarp();

        float fx = sx[j]-cx, fy = sy[j]-cy, fz = sz[j]-cz;
        float p0 = points[(b*3+0)*NN + j];
        float p1 = points[(b*3+1)*NN + j];
        float p2 = points[(b*3+2)*NN + j];

        size_t base = ((size_t)(b*SS + s)*NSAMP + lane) * 8;
        *(float4*)(g_feat + base)     = make_float4(fx, fy, fz, p0);
        *(float4*)(g_feat + base + 4) = make_float4(p1, p2, 0.f, 0.f);

        float fv[6] = {fx, fy, fz, p0, p1, p2};
        int k = 0;
        #pragma unroll
        for (int c = 0; c < 6; c++) {
            s1[c] += fv[c];
            #pragma unroll
            for (int c2 = 0; c2 <= c; c2++) s2[k++] += fv[c]*fv[c2];
        }
    }

    __shared__ float red[27];
    if (tid < 27) red[tid] = 0.f;
    __syncthreads();
    #pragma unroll
    for (int i = 0; i < 6; i++) {
        float v = s1[i];
        for (int off = 16; off; off >>= 1) v += __shfl_down_sync(0xffffffffu, v, off);
        if (lane == 0) atomicAdd(&red[i], v);
    }
    #pragma unroll
    for (int i = 0; i < 21; i++) {
        float v = s2[i];
        for (int off = 16; off; off >>= 1) v += __shfl_down_sync(0xffffffffu, v, off);
        if (lane == 0) atomicAdd(&red[6+i], v);
    }
    __syncthreads();
    if (tid < 6)       atomicAdd(&g_fsum[tid], red[tid]);
    else if (tid < 27) atomicAdd(&g_fmom[tid-6], red[tid]);
}

// ---------------- BN1 fold helper ----------------
static __device__ __forceinline__ void bn1_fold_block(
        const float* __restrict__ W1, const float* __restrict__ g1,
        const float* __restrict__ b1, float* sW1, float* sB1,
        float* sMu, float* sC, int t) {
    if (t == 0) {
        const float inv = 1.0f / (float)NSAMPLES;
        for (int c = 0; c < 6; c++) sMu[c] = g_fsum[c]*inv;
        int k = 0;
        for (int c = 0; c < 6; c++)
            for (int c2 = 0; c2 <= c; c2++) {
                float v = g_fmom[k++]*inv; sC[c*6+c2] = v; sC[c2*6+c] = v;
            }
    }
    __syncthreads();
    if (t < 64) {
        float w[6];
        #pragma unroll
        for (int c = 0; c < 6; c++) w[c] = W1[t*6+c];
        float mean = 0.f;
        #pragma unroll
        for (int c = 0; c < 6; c++) mean += w[c]*sMu[c];
        float e2 = 0.f;
        #pragma unroll
        for (int c = 0; c < 6; c++) {
            float tt = 0.f;
            #pragma unroll
            for (int c2 = 0; c2 < 6; c2++) tt += sC[c*6+c2]*w[c2];
            e2 += w[c]*tt;
        }
        float var = fmaxf(e2 - mean*mean, 0.f);
        float sc = g1[t]*rsqrtf(var + BNEPS);
        #pragma unroll
        for (int c = 0; c < 6; c++) sW1[t*6+c] = w[c]*sc;
        sB1[t] = b1[t] - mean*sc;
    }
    __syncthreads();
}

// ---------------- K2: stats — h1 mean + f32x2 SYRK (R8-proven); BN2 tail ----
#define P1PAD 134
#define BW 65
__global__ __launch_bounds__(256) void k_stats(const float* __restrict__ W1,
                                               const float* __restrict__ g1,
                                               const float* __restrict__ b1,
                                               const float* __restrict__ W2,
                                               const float* __restrict__ g2,
                                               const float* __restrict__ b2) {
    extern __shared__ float sm[];
    float* sW1  = sm;
    float* sB1  = sm + 384;
    float* ssum = sm + 448;
    float* sMu  = sm + 512;
    float* sC   = sm + 518;
    float* sH   = sm + 560;

    int t = threadIdx.x;
    if (t < 64) ssum[t] = 0.f;
    bn1_fold_block(W1, g1, b1, sW1, sB1, sMu, sC, t);

    int to = t & 15, ts = t >> 4;
    ull accM[16];
    #pragma unroll
    for (int i = 0; i < 16; i++) accM[i] = 0ull;

    const ull* ra[4]; const ull* rb[4];
    #pragma unroll
    for (int i = 0; i < 4; i++) ra[i] = (const ull*)&sH[(ts + 16*i)*P1PAD];
    #pragma unroll
    for (int j = 0; j < 4; j++) rb[j] = (const ull*)&sH[(to + 16*j)*P1PAD];

    for (int tile = blockIdx.x; tile < NTILES; tile += gridDim.x) {
        size_t s0 = (size_t)tile * 128;
        {
            int s = t & 127, kb = t >> 7;
            const float* fp = g_feat + (s0 + s)*8;
            float4 f0 = *(const float4*)fp;
            float4 f1 = *(const float4*)(fp + 4);
            float f[6] = {f0.x, f0.y, f0.z, f0.w, f1.x, f1.y};
            #pragma unroll 8
            for (int kk = 0; kk < 32; kk++) {
                int k = kb*32 + kk;
                float a = sB1[k];
                #pragma unroll
                for (int c = 0; c < 6; c++) a += f[c]*sW1[k*6+c];
                sH[k*P1PAD + s] = fmaxf(a, 0.f);
            }
        }
        __syncthreads();
        {
            int k = t & 63, q = t >> 6;
            float local = 0.f;
            #pragma unroll 8
            for (int m = 0; m < 32; m++) local += sH[k*P1PAD + q*32 + m];
            atomicAdd(&ssum[k], local);
        }
        #pragma unroll 2
        for (int s2 = 0; s2 < 64; s2++) {
            ull ha[4], hb[4];
            #pragma unroll
            for (int i = 0; i < 4; i++) ha[i] = ra[i][s2];
            #pragma unroll
            for (int j = 0; j < 4; j++) hb[j] = rb[j][s2];
            #pragma unroll
            for (int i = 0; i < 4; i++)
                #pragma unroll
                for (int j = 0; j < 4; j++) fma2(accM[i*4+j], ha[i], hb[j]);
        }
        __syncthreads();
    }

    #pragma unroll
    for (int i = 0; i < 4; i++)
        #pragma unroll
        for (int j = 0; j < 4; j++)
            atomicAdd(&g_M[(ts + 16*i)*64 + (to + 16*j)], hadd2(accM[i*4+j]));
    __syncthreads();
    if (t < 64) atomicAdd(&g_h1sum[t], ssum[t]);

    // ---- last-block BN2 tail ----
    __threadfence();
    __syncthreads();
    __shared__ unsigned amLast;
    if (t == 0) amLast = (atomicAdd(&g_cnt, 1u) == gridDim.x - 1u) ? 1u : 0u;
    __syncthreads();
    if (!amLast) return;

    if (t < 64) {
        #pragma unroll
        for (int c = 0; c < 6; c++) g_W1s[t*6+c] = sW1[t*6+c];
        g_b1s[t] = sB1[t];
    }
    __syncthreads();

    float* sM    = sH;
    float* sW    = sH + 4096;
    float* hm    = sH + 8256;
    float* partm = sm;
    float* partq = sm + 256;

    const float inv = 1.0f / (float)NSAMPLES;
    for (int i = t; i < 4096; i += 256) {
        sM[i] = __ldcg(&g_M[i]);
        sW[(i >> 6)*BW + (i & 63)] = W2[i];
    }
    if (t < 64) hm[t] = __ldcg(&g_h1sum[t]) * inv;
    __syncthreads();

    int o = t & 63, q = t >> 6;
    const float* w = &sW[o*BW];
    float lm = 0.f, lq = 0.f;
    for (int k = q*16; k < q*16 + 16; k++) {
        float wk = w[k];
        lm += wk*hm[k];
        float s = 0.f;
        #pragma unroll 8
        for (int k2 = 0; k2 < 64; k2++) s += sM[k*64 + k2]*w[k2];
        lq += wk*s;
    }
    partm[t] = lm; partq[t] = lq;
    __syncthreads();
    if (t < 64) {
        float m  = partm[t] + partm[t+64] + partm[t+128] + partm[t+192];
        float qv = (partq[t] + partq[t+64] + partq[t+128] + partq[t+192]) * inv;
        float var = fmaxf(qv - m*m, 0.f);
        float sc = g2[t]*rsqrtf(var + BNEPS);
        g_sc2[t] = sc; g_sh2[t] = b2[t] - m*sc;
    }
}

// ---------------- K3: HMMA fused layer — GEMM2 split, occ 3 ------------------
#define SM_W2H 4096
#define SM_W3H 12288
#define SM_HB  28672
#define SM_RMX 45056
#define SM_RMN 49152
#define SM_MMA_TOTAL 53248

__global__ __launch_bounds__(256, 3) void k_mma(const float* __restrict__ W2,
                                                const float* __restrict__ W3) {
    extern __shared__ char smc[];
    float* smf = (float*)smc;
    uint32_t sbase = smem_to_u32(smc);
    int t = threadIdx.x, w = t >> 5, lane = t & 31;

    float* sW1  = smf;
    float* sB1  = smf + 384;
    float* sc2s = smf + 448;
    float* sh2s = smf + 512;
    float* csum = smf + 576;
    float* csq  = smf + 704;
    float* rmax = (float*)(smc + SM_RMX);
    float* rmin = (float*)(smc + SM_RMN);

    for (int i = t; i < 384; i += 256) sW1[i] = g_W1s[i];
    if (t < 64) { sB1[t] = g_b1s[t]; sc2s[t] = g_sc2[t]; sh2s[t] = g_sh2[t]; }
    if (t < 128){ csum[t] = 0.f; csq[t] = 0.f; }
    for (int i = t; i < 2048; i += 256) {
        int o = i >> 5, kk = (i & 31)*2;
        __half2 hv = __floats2half2_rn(W2[o*64 + kk], W2[o*64 + kk + 1]);
        *(uint32_t*)(smc + SM_W2H + swz((uint32_t)(o*128 + kk*2))) = *(uint32_t*)&hv;
    }
    for (int i = t; i < 4096; i += 256) {
        int o = i >> 5, kk = (i & 31)*2;
        __half2 hv = __floats2half2_rn(W3[o*64 + kk], W3[o*64 + kk + 1]);
        *(uint32_t*)(smc + SM_W3H + swz((uint32_t)(o*128 + kk*2))) = *(uint32_t*)&hv;
    }

    size_t s0 = (size_t)blockIdx.x * 128;

    // step A: h1 fp32 -> fp16 swizzled; 2 threads per sample
    {
        int srow = w*16 + (lane >> 1), kb = lane & 1;
        const float* fp = g_feat + (s0 + srow)*8;
        float4 f0 = *(const float4*)fp;
        float4 f1 = *(const float4*)(fp + 4);
        float f[6] = {f0.x, f0.y, f0.z, f0.w, f1.x, f1.y};
        #pragma unroll
        for (int m = 0; m < 4; m++) {
            uint32_t pk[4];
            #pragma unroll
            for (int q = 0; q < 4; q++) {
                int k = kb*32 + m*8 + q*2;
                float a0 = sB1[k], a1 = sB1[k+1];
                #pragma unroll
                for (int c = 0; c < 6; c++) {
                    a0 += f[c]*sW1[k*6+c];
                    a1 += f[c]*sW1[(k+1)*6+c];
                }
                __half2 hv = __floats2half2_rn(fmaxf(a0, 0.f), fmaxf(a1, 0.f));
                pk[q] = *(uint32_t*)&hv;
            }
            *(uint4*)(smc + SM_HB + swz((uint32_t)(srow*128 + kb*64 + m*16))) =
                make_uint4(pk[0], pk[1], pk[2], pk[3]);
        }
    }
    __syncthreads();

    int m0 = w*16;
    uint32_t hbB = sbase + SM_HB, w2B = sbase + SM_W2H, w3B = sbase + SM_W3H;
    int arow = m0 + (lane & 15);
    int acolb = ((lane >> 4) & 1) * 16;
    int b4row = ((lane >> 4) << 3) + (lane & 7);
    int b4colb = ((lane >> 3) & 1) * 16;

    // GEMM1: 8 n-tiles via 4 x4-loads
    {
        float acc1[8][4];
        #pragma unroll
        for (int j = 0; j < 8; j++)
            #pragma unroll
            for (int i = 0; i < 4; i++) acc1[j][i] = 0.f;
        #pragma unroll
        for (int ks = 0; ks < 4; ks++) {
            int k0b = ks*32;
            uint32_t a[4];
            ldsm_x4(a, hbB + swz((uint32_t)(arow*128 + k0b + acolb)));
            #pragma unroll
            for (int u = 0; u < 4; u++) {
                uint32_t b4[4];
                ldsm_x4(b4, w2B + swz((uint32_t)((u*16 + b4row)*128 + k0b + b4colb)));
                uint32_t b0[2] = {b4[0], b4[1]};
                uint32_t b1[2] = {b4[2], b4[3]};
                mma16816(acc1[2*u],   a, b0);
                mma16816(acc1[2*u+1], a, b1);
            }
        }
        __syncwarp();
        // epilogue1: bn2+relu -> fp16 h2 into own rows
        int r0 = m0 + (lane >> 2);
        #pragma unroll
        for (int j = 0; j < 8; j++) {
            int o = 8*j + 2*(lane & 3);
            float sc0 = sc2s[o], sh0 = sh2s[o], sc1 = sc2s[o+1], sh1 = sh2s[o+1];
            float y0 = fmaxf(acc1[j][0]*sc0 + sh0, 0.f);
            float y1 = fmaxf(acc1[j][1]*sc1 + sh1, 0.f);
            float y2 = fmaxf(acc1[j][2]*sc0 + sh0, 0.f);
            float y3 = fmaxf(acc1[j][3]*sc1 + sh1, 0.f);
            __half2 h01 = __floats2half2_rn(y0, y1);
            __half2 h23 = __floats2half2_rn(y2, y3);
            *(uint32_t*)(smc + SM_HB + swz((uint32_t)(r0*128 + o*2)))     = *(uint32_t*)&h01;
            *(uint32_t*)(smc + SM_HB + swz((uint32_t)((r0+8)*128 + o*2))) = *(uint32_t*)&h23;
        }
    }
    __syncwarp();

    // GEMM2: two passes of 8 n-tiles (halves of the 128 output channels);
    // 32 live accumulators per pass -> fits 3 blocks/SM register budget.
    #pragma unroll 1
    for (int half = 0; half < 2; half++) {
        float acc[8][4];
        #pragma unroll
        for (int j = 0; j < 8; j++)
            #pragma unroll
            for (int i = 0; i < 4; i++) acc[j][i] = 0.f;
        uint32_t w3half = w3B + (uint32_t)half*8192;   // 64 rows * 128B
        #pragma unroll
        for (int ks = 0; ks < 4; ks++) {
            int k0b = ks*32;
            uint32_t a[4];
            ldsm_x4(a, hbB + swz((uint32_t)(arow*128 + k0b + acolb)));
            #pragma unroll
            for (int u = 0; u < 4; u++) {
                uint32_t b4[4];
                ldsm_x4(b4, w3half + swz((uint32_t)((u*16 + b4row)*128 + k0b + b4colb)));
                uint32_t b0[2] = {b4[0], b4[1]};
                uint32_t b1[2] = {b4[2], b4[3]};
                mma16816(acc[2*u],   a, b0);
                mma16816(acc[2*u+1], a, b1);
            }
        }
        // epilogue: butterfly reduce -> group max/min + stats
        #pragma unroll
        for (int j = 0; j < 8; j++) {
            float d0 = acc[j][0], d1 = acc[j][1], d2 = acc[j][2], d3 = acc[j][3];
            float mx0 = fmaxf(d0, d2), mx1 = fmaxf(d1, d3);
            float mn0 = fminf(d0, d2), mn1 = fminf(d1, d3);
            float ps0 = d0 + d2, ps1 = d1 + d3;
            float pq0 = d0*d0 + d2*d2, pq1 = d1*d1 + d3*d3;
            #pragma unroll
            for (int off = 4; off < 32; off <<= 1) {
                mx0 = fmaxf(mx0, __shfl_xor_sync(0xffffffffu, mx0, off));
                mx1 = fmaxf(mx1, __shfl_xor_sync(0xffffffffu, mx1, off));
                mn0 = fminf(mn0, __shfl_xor_sync(0xffffffffu, mn0, off));
                mn1 = fminf(mn1, __shfl_xor_sync(0xffffffffu, mn1, off));
                ps0 += __shfl_xor_sync(0xffffffffu, ps0, off);
                ps1 += __shfl_xor_sync(0xffffffffu, ps1, off);
                pq0 += __shfl_xor_sync(0xffffffffu, pq0, off);
                pq1 += __shfl_xor_sync(0xffffffffu, pq1, off);
            }
            if (lane < 4) {
                int o = half*64 + 8*j + 2*lane;
                rmax[w*128 + o]     = mx0;
                rmax[w*128 + o + 1] = mx1;
                rmin[w*128 + o]     = mn0;
                rmin[w*128 + o + 1] = mn1;
                atomicAdd(&csum[o],   ps0);
                atomicAdd(&csum[o+1], ps1);
                atomicAdd(&csq[o],    pq0);
                atomicAdd(&csq[o+1],  pq1);
            }
        }
    }
    __syncthreads();

    for (int v = t; v < 512; v += 256) {
        int g = v >> 7, o = v & 127;
        float mx = fmaxf(rmax[(2*g)*128 + o], rmax[(2*g+1)*128 + o]);
        float mn = fminf(rmin[(2*g)*128 + o], rmin[(2*g+1)*128 + o]);
        g_gmax[(s0/32 + g)*128 + o] = mx;
        g_gmin[(s0/32 + g)*128 + o] = mn;
    }
    if (t < 128) { atomicAdd(&g_x3sum[t], csum[t]); atomicAdd(&g_x3sq[t], csq[t]); }
}

// ---------------- K4: bn3 (inline) + relu on group max/min, transposed out ----
__global__ void k_out2(const float* __restrict__ g3, const float* __restrict__ b3,
                       float* __restrict__ out2) {
    __shared__ float tr[32*129];
    __shared__ float ssc[128], ssh[128];
    int b = blockIdx.y;
    int s0 = blockIdx.x * 32;
    int t = threadIdx.x;
    if (t < 128) {
        const float inv = 1.0f / (float)NSAMPLES;
        float m = g_x3sum[t]*inv;
        float v = fmaxf(g_x3sq[t]*inv - m*m, 0.f);
        float sc = g3[t]*rsqrtf(v + BNEPS);
        ssc[t] = sc; ssh[t] = b3[t] - m*sc;
    }
    __syncthreads();
    for (int i = t; i < 32*128; i += 256) {
        int gi = i >> 7, o = i & 127;
        float sc = ssc[o], sh = ssh[o];
        size_t g = (size_t)(b*SS + s0 + gi);
        float v = (sc >= 0.f) ? g_gmax[g*128 + o] : g_gmin[g*128 + o];
        tr[gi*129 + o] = fmaxf(sc*v + sh, 0.f);
    }
    __syncthreads();
    for (int i = t; i < 32*128; i += 256) {
        int o = i >> 5, si = i & 31;
        out2[((size_t)(b*128 + o))*SS + s0 + si] = tr[si*129 + o];
    }
}

// ---------------- launch ----------------
extern "C" void kernel_launch(void* const* d_in, const int* in_sizes, int n_in,
                              void* d_out, int out_size) {
    const float* xyz    = (const float*)d_in[0];
    const float* points = (const float*)d_in[1];
    const int*   fps    = (const int*)  d_in[2];
    const float* W1 = (const float*)d_in[3];
    const float* g1 = (const float*)d_in[4];
    const float* b1 = (const float*)d_in[5];
    const float* W2 = (const float*)d_in[6];
    const float* g2 = (const float*)d_in[7];
    const float* b2 = (const float*)d_in[8];
    const float* W3 = (const float*)d_in[9];
    const float* g3 = (const float*)d_in[10];
    const float* b3 = (const float*)d_in[11];

    float* out1 = (float*)d_out;
    float* out2 = (float*)d_out + (size_t)BB*3*SS;

    const int SMEM_BALL  = (3*NN)*4 + 8*32*4;
    const int SMEM_STATS = (560 + 64*P1PAD)*4;

    cudaFuncSetAttribute(k_ball,  cudaFuncAttributeMaxDynamicSharedMemorySize, SMEM_BALL);
    cudaFuncSetAttribute(k_stats, cudaFuncAttributeMaxDynamicSharedMemorySize, SMEM_STATS);
    cudaFuncSetAttribute(k_mma,   cudaFuncAttributeMaxDynamicSharedMemorySize, SM_MMA_TOTAL);

    k_zero<<<1, 256>>>();
    k_ball<<<dim3(SS/32, BB), 256, SMEM_BALL>>>(xyz, points, fps, out1);
    k_stats<<<592, 256, SMEM_STATS>>>(W1, g1, b1, W2, g2, b2);
    k_mma<<<NTILES, 256, SM_MMA_TOTAL>>>(W2, W3);
    k_out2<<<dim3(SS/32, BB), 256>>>(g3, b3, out2);
}

// round 15
// speedup vs baseline: 1.6982x; 1.3113x over previous
#include <cuda_runtime.h>
#include <cuda_fp16.h>
#include <math.h>
#include <stdint.h>

#define BB 8
#define NN 8192
#define SS 2048
#define NSAMP 32
#define NSAMPLES (BB*SS*NSAMP)   /* 524288 */
#define NGROUPS (BB*SS)          /* 16384  */
#define NTILES (NSAMPLES/128)    /* 4096   */
#define R2 0.04f
#define BNEPS 1e-5f

typedef unsigned long long ull;

// ---------------- device scratch ----------------
__device__ float g_feat[(size_t)NSAMPLES*8];
__device__ float g_gmax[(size_t)NGROUPS*128];
__device__ float g_gmin[(size_t)NGROUPS*128];
__device__ float g_fsum[6];
__device__ float g_fmom[21];
__device__ float g_x2s[64], g_x2q[64];           // BN2 stats (direct from x2)
__device__ float g_x3sum[128], g_x3sq[128];
__device__ float g_W1s[64*6], g_b1s[64];
__device__ float g_sc2[64], g_sh2[64];
__device__ unsigned g_cnt;

// ---------------- mma.sync helpers ----------------
static __device__ __forceinline__ uint32_t smem_to_u32(const void* p) {
    uint32_t a;
    asm("{ .reg .u64 tmp; cvta.to.shared.u64 tmp, %1; cvt.u32.u64 %0, tmp; }"
        : "=r"(a) : "l"(p));
    return a;
}
static __device__ __forceinline__ uint32_t swz(uint32_t off) {
    return off ^ ((off >> 3) & 0x70);
}
static __device__ __forceinline__ void ldsm_x4(uint32_t (&a)[4], uint32_t addr) {
    asm volatile("ldmatrix.sync.aligned.m8n8.x4.shared.b16 {%0,%1,%2,%3}, [%4];"
        : "=r"(a[0]), "=r"(a[1]), "=r"(a[2]), "=r"(a[3]) : "r"(addr));
}
static __device__ __forceinline__ void mma16816(float (&d)[4], const uint32_t (&a)[4],
                                                const uint32_t (&b)[2]) {
    asm volatile("mma.sync.aligned.m16n8k16.row.col.f32.f16.f16.f32 "
        "{%0,%1,%2,%3}, {%4,%5,%6,%7}, {%8,%9}, {%0,%1,%2,%3};"
        : "+f"(d[0]), "+f"(d[1]), "+f"(d[2]), "+f"(d[3])
        : "r"(a[0]), "r"(a[1]), "r"(a[2]), "r"(a[3]), "r"(b[0]), "r"(b[1]));
}

// ---------------- K0: zero accumulators ----------------
__global__ void k_zero() {
    int t = threadIdx.x;
    if (t < 6)  g_fsum[t] = 0.f;
    if (t < 21) g_fmom[t] = 0.f;
    if (t < 64) { g_x2s[t] = 0.f; g_x2q[t] = 0.f; }
    if (t < 128){ g_x3sum[t] = 0.f; g_x3sq[t] = 0.f; }
    if (t == 0) g_cnt = 0u;
}

// ---------------- K1: ball query + feat + feat moments + out1 ----------------
__global__ __launch_bounds__(256) void k_ball(const float* __restrict__ xyz,
                                              const float* __restrict__ points,
                                              const int*   __restrict__ fps,
                                              float* __restrict__ out1) {
    extern __shared__ float sm[];
    float* sx = sm;
    float* sy = sm + NN;
    float* sz = sm + 2*NN;
    int*   fnd = (int*)(sm + 3*NN);

    int b = blockIdx.y;
    int qbase = blockIdx.x * 32;
    int tid = threadIdx.x;

    for (int i = tid; i < NN; i += 256) {
        sx[i] = xyz[(b*3+0)*NN + i];
        sy[i] = xyz[(b*3+1)*NN + i];
        sz[i] = xyz[(b*3+2)*NN + i];
    }
    __syncthreads();

    int w = tid >> 5, lane = tid & 31;
    int* f = fnd + w*32;
    unsigned lmask = (1u << lane) - 1u;

    float s1[6], s2[21];
    #pragma unroll
    for (int i = 0; i < 6; i++)  s1[i] = 0.f;
    #pragma unroll
    for (int i = 0; i < 21; i++) s2[i] = 0.f;

    for (int qi = 0; qi < 4; qi++) {
        int s = qbase + w*4 + qi;
        int cidx = fps[b*SS + s];
        float cx = sx[cidx], cy = sy[cidx], cz = sz[cidx];
        if (lane == 0) {
            out1[(b*3+0)*SS + s] = cx;
            out1[(b*3+1)*SS + s] = cy;
            out1[(b*3+2)*SS + s] = cz;
        }
        int cnt = 0;
        for (int chunk = 0; chunk < NN/32; chunk++) {
            int j = chunk*32 + lane;
            float dx = __fsub_rn(sx[j], cx);
            float dy = __fsub_rn(sy[j], cy);
            float dz = __fsub_rn(sz[j], cz);
            float d2 = __fadd_rn(__fadd_rn(__fmul_rn(dx,dx), __fmul_rn(dy,dy)),
                                 __fmul_rn(dz,dz));
            bool hit = (d2 <= R2);
            unsigned mask = __ballot_sync(0xffffffffu, hit);
            if (hit) {
                int pos = cnt + __popc(mask & lmask);
                if (pos < 32) f[pos] = j;
            }
            cnt += __popc(mask);
            if (cnt >= 32) break;
        }
        __syncwarp();
        int j = (lane < cnt) ? f[lane] : f[0];
        __syncwarp();

        float fx = sx[j]-cx, fy = sy[j]-cy, fz = sz[j]-cz;
        float p0 = points[(b*3+0)*NN + j];
        float p1 = points[(b*3+1)*NN + j];
        float p2 = points[(b*3+2)*NN + j];

        size_t base = ((size_t)(b*SS + s)*NSAMP + lane) * 8;
        *(float4*)(g_feat + base)     = make_float4(fx, fy, fz, p0);
        *(float4*)(g_feat + base + 4) = make_float4(p1, p2, 0.f, 0.f);

        float fv[6] = {fx, fy, fz, p0, p1, p2};
        int k = 0;
        #pragma unroll
        for (int c = 0; c < 6; c++) {
            s1[c] += fv[c];
            #pragma unroll
            for (int c2 = 0; c2 <= c; c2++) s2[k++] += fv[c]*fv[c2];
        }
    }

    __shared__ float red[27];
    if (tid < 27) red[tid] = 0.f;
    __syncthreads();
    #pragma unroll
    for (int i = 0; i < 6; i++) {
        float v = s1[i];
        for (int off = 16; off; off >>= 1) v += __shfl_down_sync(0xffffffffu, v, off);
        if (lane == 0) atomicAdd(&red[i], v);
    }
    #pragma unroll
    for (int i = 0; i < 21; i++) {
        float v = s2[i];
        for (int off = 16; off; off >>= 1) v += __shfl_down_sync(0xffffffffu, v, off);
        if (lane == 0) atomicAdd(&red[6+i], v);
    }
    __syncthreads();
    if (tid < 6)       atomicAdd(&g_fsum[tid], red[tid]);
    else if (tid < 27) atomicAdd(&g_fmom[tid-6], red[tid]);
}

// ---------------- BN1 fold helper ----------------
static __device__ __forceinline__ void bn1_fold_block(
        const float* __restrict__ W1, const float* __restrict__ g1,
        const float* __restrict__ b1, float* sW1, float* sB1,
        float* sMu, float* sC, int t) {
    if (t == 0) {
        const float inv = 1.0f / (float)NSAMPLES;
        for (int c = 0; c < 6; c++) sMu[c] = g_fsum[c]*inv;
        int k = 0;
        for (int c = 0; c < 6; c++)
            for (int c2 = 0; c2 <= c; c2++) {
                float v = g_fmom[k++]*inv; sC[c*6+c2] = v; sC[c2*6+c] = v;
            }
    }
    __syncthreads();
    if (t < 64) {
        float w[6];
        #pragma unroll
        for (int c = 0; c < 6; c++) w[c] = W1[t*6+c];
        float mean = 0.f;
        #pragma unroll
        for (int c = 0; c < 6; c++) mean += w[c]*sMu[c];
        float e2 = 0.f;
        #pragma unroll
        for (int c = 0; c < 6; c++) {
            float tt = 0.f;
            #pragma unroll
            for (int c2 = 0; c2 < 6; c2++) tt += sC[c*6+c2]*w[c2];
            e2 += w[c]*tt;
        }
        float var = fmaxf(e2 - mean*mean, 0.f);
        float sc = g1[t]*rsqrtf(var + BNEPS);
        #pragma unroll
        for (int c = 0; c < 6; c++) sW1[t*6+c] = w[c]*sc;
        sB1[t] = b1[t] - mean*sc;
    }
    __syncthreads();
}

// ---------------- K2: stats — BN2 moments via HMMA GEMM1 (x2 = h1·W2ᵀ) ------
// Grid-stride; weights staged once per block. Per-lane Σx2/Σx2² accumulate in
// registers across all tiles; butterfly + smem combine + global atomics once.
#define SM2_W2H 4096
#define SM2_HB  12288
#define SM2_TOTAL 28672
__global__ __launch_bounds__(256) void k_stats(const float* __restrict__ W1,
                                               const float* __restrict__ g1,
                                               const float* __restrict__ b1,
                                               const float* __restrict__ W2,
                                               const float* __restrict__ g2,
                                               const float* __restrict__ b2) {
    extern __shared__ float smf[];
    char* smc = (char*)smf;
    uint32_t sbase = smem_to_u32(smc);
    float* sW1  = smf;          // 384
    float* sB1  = smf + 384;    // 64
    float* sMu  = smf + 448;    // 6
    float* sC   = smf + 454;    // 36
    float* csum = smf + 512;    // 64
    float* csq  = smf + 576;    // 64  (ends 640 floats = 2560 B < 4096)

    int t = threadIdx.x, w = t >> 5, lane = t & 31;
    if (t < 64) { csum[t] = 0.f; csq[t] = 0.f; }
    bn1_fold_block(W1, g1, b1, sW1, sB1, sMu, sC, t);

    // stage W2 fp16 swizzled (once per block)
    for (int i = t; i < 2048; i += 256) {
        int o = i >> 5, kk = (i & 31)*2;
        __half2 hv = __floats2half2_rn(W2[o*64 + kk], W2[o*64 + kk + 1]);
        *(uint32_t*)(smc + SM2_W2H + swz((uint32_t)(o*128 + kk*2))) = *(uint32_t*)&hv;
    }
    __syncthreads();

    int m0 = w*16;
    uint32_t hbB = sbase + SM2_HB, w2B = sbase + SM2_W2H;
    int arow = m0 + (lane & 15);
    int acolb = ((lane >> 4) & 1) * 16;
    int b4row = ((lane >> 4) << 3) + (lane & 7);
    int b4colb = ((lane >> 3) & 1) * 16;
    int srow = w*16 + (lane >> 1), kb = lane & 1;

    float psum[16], pqsum[16];   // [j][0/1]: cols o=8j+2(lane&3), +1
    #pragma unroll
    for (int i = 0; i < 16; i++) { psum[i] = 0.f; pqsum[i] = 0.f; }

    for (int tile = blockIdx.x; tile < NTILES; tile += gridDim.x) {
        size_t s0 = (size_t)tile * 128;
        // build fp16 h1 (identical to k_mma step A)
        {
            const float* fp = g_feat + (s0 + srow)*8;
            float4 f0 = *(const float4*)fp;
            float4 f1 = *(const float4*)(fp + 4);
            float f[6] = {f0.x, f0.y, f0.z, f0.w, f1.x, f1.y};
            #pragma unroll
            for (int m = 0; m < 4; m++) {
                uint32_t pk[4];
                #pragma unroll
                for (int q = 0; q < 4; q++) {
                    int k = kb*32 + m*8 + q*2;
                    float a0 = sB1[k], a1 = sB1[k+1];
                    #pragma unroll
                    for (int c = 0; c < 6; c++) {
                        a0 += f[c]*sW1[k*6+c];
                        a1 += f[c]*sW1[(k+1)*6+c];
                    }
                    __half2 hv = __floats2half2_rn(fmaxf(a0, 0.f), fmaxf(a1, 0.f));
                    pk[q] = *(uint32_t*)&hv;
                }
                *(uint4*)(smc + SM2_HB + swz((uint32_t)(srow*128 + kb*64 + m*16))) =
                    make_uint4(pk[0], pk[1], pk[2], pk[3]);
            }
        }
        __syncthreads();
        // GEMM1: x2 = h1 · W2^T (identical structure to k_mma GEMM1)
        float acc[8][4];
        #pragma unroll
        for (int j = 0; j < 8; j++)
            #pragma unroll
            for (int i = 0; i < 4; i++) acc[j][i] = 0.f;
        #pragma unroll
        for (int ks = 0; ks < 4; ks++) {
            int k0b = ks*32;
            uint32_t a[4];
            ldsm_x4(a, hbB + swz((uint32_t)(arow*128 + k0b + acolb)));
            #pragma unroll
            for (int u = 0; u < 4; u++) {
                uint32_t b4[4];
                ldsm_x4(b4, w2B + swz((uint32_t)((u*16 + b4row)*128 + k0b + b4colb)));
                uint32_t b0[2] = {b4[0], b4[1]};
                uint32_t b1v[2] = {b4[2], b4[3]};
                mma16816(acc[2*u],   a, b0);
                mma16816(acc[2*u+1], a, b1v);
            }
        }
        // accumulate moments (register-resident across tiles)
        #pragma unroll
        for (int j = 0; j < 8; j++) {
            float d0 = acc[j][0], d1 = acc[j][1], d2 = acc[j][2], d3 = acc[j][3];
            psum[2*j]   += d0 + d2;
            psum[2*j+1] += d1 + d3;
            pqsum[2*j]   += d0*d0 + d2*d2;
            pqsum[2*j+1] += d1*d1 + d3*d3;
        }
        __syncthreads();   // all GEMM reads done before next tile's h-build
    }

    // butterfly over lane>>2 (rows), combine in smem, flush once
    #pragma unroll
    for (int j = 0; j < 8; j++) {
        float ps0 = psum[2*j], ps1 = psum[2*j+1];
        float pq0 = pqsum[2*j], pq1 = pqsum[2*j+1];
        #pragma unroll
        for (int off = 4; off < 32; off <<= 1) {
            ps0 += __shfl_xor_sync(0xffffffffu, ps0, off);
            ps1 += __shfl_xor_sync(0xffffffffu, ps1, off);
            pq0 += __shfl_xor_sync(0xffffffffu, pq0, off);
            pq1 += __shfl_xor_sync(0xffffffffu, pq1, off);
        }
        if (lane < 4) {
            int o = 8*j + 2*lane;
            atomicAdd(&csum[o],   ps0);
            atomicAdd(&csum[o+1], ps1);
            atomicAdd(&csq[o],    pq0);
            atomicAdd(&csq[o+1],  pq1);
        }
    }
    __syncthreads();
    if (t < 64) { atomicAdd(&g_x2s[t], csum[t]); atomicAdd(&g_x2q[t], csq[t]); }

    // ---- last-block BN2 tail ----
    __threadfence();
    __syncthreads();
    __shared__ unsigned amLast;
    if (t == 0) amLast = (atomicAdd(&g_cnt, 1u) == gridDim.x - 1u) ? 1u : 0u;
    __syncthreads();
    if (!amLast) return;

    if (t < 64) {
        #pragma unroll
        for (int c = 0; c < 6; c++) g_W1s[t*6+c] = sW1[t*6+c];
        g_b1s[t] = sB1[t];
        const float inv = 1.0f / (float)NSAMPLES;
        float m  = __ldcg(&g_x2s[t]) * inv;
        float qv = __ldcg(&g_x2q[t]) * inv;
        float var = fmaxf(qv - m*m, 0.f);
        float sc = g2[t]*rsqrtf(var + BNEPS);
        g_sc2[t] = sc; g_sh2[t] = b2[t] - m*sc;
    }
}

// ---------------- K3: HMMA fused layer (R14-proven, frozen) ------------------
#define SM_W2H 4096
#define SM_W3H 12288
#define SM_HB  28672
#define SM_RMX 45056
#define SM_RMN 49152
#define SM_MMA_TOTAL 53248

__global__ __launch_bounds__(256, 3) void k_mma(const float* __restrict__ W2,
                                                const float* __restrict__ W3) {
    extern __shared__ char smc[];
    float* smf = (float*)smc;
    uint32_t sbase = smem_to_u32(smc);
    int t = threadIdx.x, w = t >> 5, lane = t & 31;

    float* sW1  = smf;
    float* sB1  = smf + 384;
    float* sc2s = smf + 448;
    float* sh2s = smf + 512;
    float* csum = smf + 576;
    float* csq  = smf + 704;
    float* rmax = (float*)(smc + SM_RMX);
    float* rmin = (float*)(smc + SM_RMN);

    for (int i = t; i < 384; i += 256) sW1[i] = g_W1s[i];
    if (t < 64) { sB1[t] = g_b1s[t]; sc2s[t] = g_sc2[t]; sh2s[t] = g_sh2[t]; }
    if (t < 128){ csum[t] = 0.f; csq[t] = 0.f; }
    for (int i = t; i < 2048; i += 256) {
        int o = i >> 5, kk = (i & 31)*2;
        __half2 hv = __floats2half2_rn(W2[o*64 + kk], W2[o*64 + kk + 1]);
        *(uint32_t*)(smc + SM_W2H + swz((uint32_t)(o*128 + kk*2))) = *(uint32_t*)&hv;
    }
    for (int i = t; i < 4096; i += 256) {
        int o = i >> 5, kk = (i & 31)*2;
        __half2 hv = __floats2half2_rn(W3[o*64 + kk], W3[o*64 + kk + 1]);
        *(uint32_t*)(smc + SM_W3H + swz((uint32_t)(o*128 + kk*2))) = *(uint32_t*)&hv;
    }

    size_t s0 = (size_t)blockIdx.x * 128;

    {
        int srow = w*16 + (lane >> 1), kb = lane & 1;
        const float* fp = g_feat + (s0 + srow)*8;
        float4 f0 = *(const float4*)fp;
        float4 f1 = *(const float4*)(fp + 4);
        float f[6] = {f0.x, f0.y, f0.z, f0.w, f1.x, f1.y};
        #pragma unroll
        for (int m = 0; m < 4; m++) {
            uint32_t pk[4];
            #pragma unroll
            for (int q = 0; q < 4; q++) {
                int k = kb*32 + m*8 + q*2;
                float a0 = sB1[k], a1 = sB1[k+1];
                #pragma unroll
                for (int c = 0; c < 6; c++) {
                    a0 += f[c]*sW1[k*6+c];
                    a1 += f[c]*sW1[(k+1)*6+c];
                }
                __half2 hv = __floats2half2_rn(fmaxf(a0, 0.f), fmaxf(a1, 0.f));
                pk[q] = *(uint32_t*)&hv;
            }
            *(uint4*)(smc + SM_HB + swz((uint32_t)(srow*128 + kb*64 + m*16))) =
                make_uint4(pk[0], pk[1], pk[2], pk[3]);
        }
    }
    __syncthreads();

    int m0 = w*16;
    uint32_t hbB = sbase + SM_HB, w2B = sbase + SM_W2H, w3B = sbase + SM_W3H;
    int arow = m0 + (lane & 15);
    int acolb = ((lane >> 4) & 1) * 16;
    int b4row = ((lane >> 4) << 3) + (lane & 7);
    int b4colb = ((lane >> 3) & 1) * 16;

    // GEMM1
    {
        float acc1[8][4];
        #pragma unroll
        for (int j = 0; j < 8; j++)
            #pragma unroll
            for (int i = 0; i < 4; i++) acc1[j][i] = 0.f;
        #pragma unroll
        for (int ks = 0; ks < 4; ks++) {
            int k0b = ks*32;
            uint32_t a[4];
            ldsm_x4(a, hbB + swz((uint32_t)(arow*128 + k0b + acolb)));
            #pragma unroll
            for (int u = 0; u < 4; u++) {
                uint32_t b4[4];
                ldsm_x4(b4, w2B + swz((uint32_t)((u*16 + b4row)*128 + k0b + b4colb)));
                uint32_t b0[2] = {b4[0], b4[1]};
                uint32_t b1[2] = {b4[2], b4[3]};
                mma16816(acc1[2*u],   a, b0);
                mma16816(acc1[2*u+1], a, b1);
            }
        }
        __syncwarp();
        int r0 = m0 + (lane >> 2);
        #pragma unroll
        for (int j = 0; j < 8; j++) {
            int o = 8*j + 2*(lane & 3);
            float sc0 = sc2s[o], sh0 = sh2s[o], sc1 = sc2s[o+1], sh1 = sh2s[o+1];
            float y0 = fmaxf(acc1[j][0]*sc0 + sh0, 0.f);
            float y1 = fmaxf(acc1[j][1]*sc1 + sh1, 0.f);
            float y2 = fmaxf(acc1[j][2]*sc0 + sh0, 0.f);
            float y3 = fmaxf(acc1[j][3]*sc1 + sh1, 0.f);
            __half2 h01 = __floats2half2_rn(y0, y1);
            __half2 h23 = __floats2half2_rn(y2, y3);
            *(uint32_t*)(smc + SM_HB + swz((uint32_t)(r0*128 + o*2)))     = *(uint32_t*)&h01;
            *(uint32_t*)(smc + SM_HB + swz((uint32_t)((r0+8)*128 + o*2))) = *(uint32_t*)&h23;
        }
    }
    __syncwarp();

    // GEMM2: two passes of 8 n-tiles
    #pragma unroll 1
    for (int half = 0; half < 2; half++) {
        float acc[8][4];
        #pragma unroll
        for (int j = 0; j < 8; j++)
            #pragma unroll
            for (int i = 0; i < 4; i++) acc[j][i] = 0.f;
        uint32_t w3half = w3B + (uint32_t)half*8192;
        #pragma unroll
        for (int ks = 0; ks < 4; ks++) {
            int k0b = ks*32;
            uint32_t a[4];
            ldsm_x4(a, hbB + swz((uint32_t)(arow*128 + k0b + acolb)));
            #pragma unroll
            for (int u = 0; u < 4; u++) {
                uint32_t b4[4];
                ldsm_x4(b4, w3half + swz((uint32_t)((u*16 + b4row)*128 + k0b + b4colb)));
                uint32_t b0[2] = {b4[0], b4[1]};
                uint32_t b1[2] = {b4[2], b4[3]};
                mma16816(acc[2*u],   a, b0);
                mma16816(acc[2*u+1], a, b1);
            }
        }
        #pragma unroll
        for (int j = 0; j < 8; j++) {
            float d0 = acc[j][0], d1 = acc[j][1], d2 = acc[j][2], d3 = acc[j][3];
            float mx0 = fmaxf(d0, d2), mx1 = fmaxf(d1, d3);
            float mn0 = fminf(d0, d2), mn1 = fminf(d1, d3);
            float ps0 = d0 + d2, ps1 = d1 + d3;
            float pq0 = d0*d0 + d2*d2, pq1 = d1*d1 + d3*d3;
            #pragma unroll
            for (int off = 4; off < 32; off <<= 1) {
                mx0 = fmaxf(mx0, __shfl_xor_sync(0xffffffffu, mx0, off));
                mx1 = fmaxf(mx1, __shfl_xor_sync(0xffffffffu, mx1, off));
                mn0 = fminf(mn0, __shfl_xor_sync(0xffffffffu, mn0, off));
                mn1 = fminf(mn1, __shfl_xor_sync(0xffffffffu, mn1, off));
                ps0 += __shfl_xor_sync(0xffffffffu, ps0, off);
                ps1 += __shfl_xor_sync(0xffffffffu, ps1, off);
                pq0 += __shfl_xor_sync(0xffffffffu, pq0, off);
                pq1 += __shfl_xor_sync(0xffffffffu, pq1, off);
            }
            if (lane < 4) {
                int o = half*64 + 8*j + 2*lane;
                rmax[w*128 + o]     = mx0;
                rmax[w*128 + o + 1] = mx1;
                rmin[w*128 + o]     = mn0;
                rmin[w*128 + o + 1] = mn1;
                atomicAdd(&csum[o],   ps0);
                atomicAdd(&csum[o+1], ps1);
                atomicAdd(&csq[o],    pq0);
                atomicAdd(&csq[o+1],  pq1);
            }
        }
    }
    __syncthreads();

    for (int v = t; v < 512; v += 256) {
        int g = v >> 7, o = v & 127;
        float mx = fmaxf(rmax[(2*g)*128 + o], rmax[(2*g+1)*128 + o]);
        float mn = fminf(rmin[(2*g)*128 + o], rmin[(2*g+1)*128 + o]);
        g_gmax[(s0/32 + g)*128 + o] = mx;
        g_gmin[(s0/32 + g)*128 + o] = mn;
    }
    if (t < 128) { atomicAdd(&g_x3sum[t], csum[t]); atomicAdd(&g_x3sq[t], csq[t]); }
}

// ---------------- K4: bn3 (inline) + relu on group max/min, transposed out ----
__global__ void k_out2(const float* __restrict__ g3, const float* __restrict__ b3,
                       float* __restrict__ out2) {
    __shared__ float tr[32*129];
    __shared__ float ssc[128], ssh[128];
    int b = blockIdx.y;
    int s0 = blockIdx.x * 32;
    int t = threadIdx.x;
    if (t < 128) {
        const float inv = 1.0f / (float)NSAMPLES;
        float m = g_x3sum[t]*inv;
        float v = fmaxf(g_x3sq[t]*inv - m*m, 0.f);
        float sc = g3[t]*rsqrtf(v + BNEPS);
        ssc[t] = sc; ssh[t] = b3[t] - m*sc;
    }
    __syncthreads();
    for (int i = t; i < 32*128; i += 256) {
        int gi = i >> 7, o = i & 127;
        float sc = ssc[o], sh = ssh[o];
        size_t g = (size_t)(b*SS + s0 + gi);
        float v = (sc >= 0.f) ? g_gmax[g*128 + o] : g_gmin[g*128 + o];
        tr[gi*129 + o] = fmaxf(sc*v + sh, 0.f);
    }
    __syncthreads();
    for (int i = t; i < 32*128; i += 256) {
        int o = i >> 5, si = i & 31;
        out2[((size_t)(b*128 + o))*SS + s0 + si] = tr[si*129 + o];
    }
}

// ---------------- launch ----------------
extern "C" void kernel_launch(void* const* d_in, const int* in_sizes, int n_in,
                              void* d_out, int out_size) {
    const float* xyz    = (const float*)d_in[0];
    const float* points = (const float*)d_in[1];
    const int*   fps    = (const int*)  d_in[2];
    const float* W1 = (const float*)d_in[3];
    const float* g1 = (const float*)d_in[4];
    const float* b1 = (const float*)d_in[5];
    const float* W2 = (const float*)d_in[6];
    const float* g2 = (const float*)d_in[7];
    const float* b2 = (const float*)d_in[8];
    const float* W3 = (const float*)d_in[9];
    const float* g3 = (const float*)d_in[10];
    const float* b3 = (const float*)d_in[11];

    float* out1 = (float*)d_out;
    float* out2 = (float*)d_out + (size_t)BB*3*SS;

    const int SMEM_BALL  = (3*NN)*4 + 8*32*4;

    cudaFuncSetAttribute(k_ball,  cudaFuncAttributeMaxDynamicSharedMemorySize, SMEM_BALL);
    cudaFuncSetAttribute(k_stats, cudaFuncAttributeMaxDynamicSharedMemorySize, SM2_TOTAL);
    cudaFuncSetAttribute(k_mma,   cudaFuncAttributeMaxDynamicSharedMemorySize, SM_MMA_TOTAL);

    k_zero<<<1, 256>>>();
    k_ball<<<dim3(SS/32, BB), 256, SMEM_BALL>>>(xyz, points, fps, out1);
    k_stats<<<592, 256, SM2_TOTAL>>>(W1, g1, b1, W2, g2, b2);
    k_mma<<<NTILES, 256, SM_MMA_TOTAL>>>(W2, W3);
    k_out2<<<dim3(SS/32, BB), 256>>>(g3, b3, out2);
}

// round 16
// speedup vs baseline: 1.7916x; 1.0550x over previous
#include <cuda_runtime.h>
#include <cuda_fp16.h>
#include <math.h>
#include <stdint.h>

#define BB 8
#define NN 8192
#define SS 2048
#define NSAMP 32
#define NSAMPLES (BB*SS*NSAMP)   /* 524288 */
#define NGROUPS (BB*SS)          /* 16384  */
#define NTILES (NSAMPLES/128)    /* 4096   */
#define R2 0.04f
#define BNEPS 1e-5f

typedef unsigned long long ull;

// ---------------- device scratch ----------------
__device__ float g_feat[(size_t)NSAMPLES*8];
__device__ __half g_x2h[(size_t)NSAMPLES*64];    // raw x2, swizzled 128B rows
__device__ float g_gmax[(size_t)NGROUPS*128];
__device__ float g_gmin[(size_t)NGROUPS*128];
__device__ float g_fsum[6];
__device__ float g_fmom[21];
__device__ float g_x2s[64], g_x2q[64];
__device__ float g_x3sum[128], g_x3sq[128];
__device__ float g_W1s[64*6], g_b1s[64];
__device__ float g_sc2[64], g_sh2[64];
__device__ unsigned g_cnt;

// ---------------- mma.sync helpers ----------------
static __device__ __forceinline__ uint32_t smem_to_u32(const void* p) {
    uint32_t a;
    asm("{ .reg .u64 tmp; cvta.to.shared.u64 tmp, %1; cvt.u32.u64 %0, tmp; }"
        : "=r"(a) : "l"(p));
    return a;
}
static __device__ __forceinline__ uint32_t swz(uint32_t off) {
    return off ^ ((off >> 3) & 0x70);
}
static __device__ __forceinline__ void ldsm_x4(uint32_t (&a)[4], uint32_t addr) {
    asm volatile("ldmatrix.sync.aligned.m8n8.x4.shared.b16 {%0,%1,%2,%3}, [%4];"
        : "=r"(a[0]), "=r"(a[1]), "=r"(a[2]), "=r"(a[3]) : "r"(addr));
}
static __device__ __forceinline__ void mma16816(float (&d)[4], const uint32_t (&a)[4],
                                                const uint32_t (&b)[2]) {
    asm volatile("mma.sync.aligned.m16n8k16.row.col.f32.f16.f16.f32 "
        "{%0,%1,%2,%3}, {%4,%5,%6,%7}, {%8,%9}, {%0,%1,%2,%3};"
        : "+f"(d[0]), "+f"(d[1]), "+f"(d[2]), "+f"(d[3])
        : "r"(a[0]), "r"(a[1]), "r"(a[2]), "r"(a[3]), "r"(b[0]), "r"(b[1]));
}

// ---------------- K0: zero accumulators ----------------
__global__ void k_zero() {
    int t = threadIdx.x;
    if (t < 6)  g_fsum[t] = 0.f;
    if (t < 21) g_fmom[t] = 0.f;
    if (t < 64) { g_x2s[t] = 0.f; g_x2q[t] = 0.f; }
    if (t < 128){ g_x3sum[t] = 0.f; g_x3sq[t] = 0.f; }
    if (t == 0) g_cnt = 0u;
}

// ---------------- K1: ball query + feat + feat moments + out1 ----------------
__global__ __launch_bounds__(256) void k_ball(const float* __restrict__ xyz,
                                              const float* __restrict__ points,
                                              const int*   __restrict__ fps,
                                              float* __restrict__ out1) {
    extern __shared__ float sm[];
    float* sx = sm;
    float* sy = sm + NN;
    float* sz = sm + 2*NN;
    int*   fnd = (int*)(sm + 3*NN);

    int b = blockIdx.y;
    int qbase = blockIdx.x * 32;
    int tid = threadIdx.x;

    for (int i = tid; i < NN; i += 256) {
        sx[i] = xyz[(b*3+0)*NN + i];
        sy[i] = xyz[(b*3+1)*NN + i];
        sz[i] = xyz[(b*3+2)*NN + i];
    }
    __syncthreads();

    int w = tid >> 5, lane = tid & 31;
    int* f = fnd + w*32;
    unsigned lmask = (1u << lane) - 1u;

    float s1[6], s2[21];
    #pragma unroll
    for (int i = 0; i < 6; i++)  s1[i] = 0.f;
    #pragma unroll
    for (int i = 0; i < 21; i++) s2[i] = 0.f;

    for (int qi = 0; qi < 4; qi++) {
        int s = qbase + w*4 + qi;
        int cidx = fps[b*SS + s];
        float cx = sx[cidx], cy = sy[cidx], cz = sz[cidx];
        if (lane == 0) {
            out1[(b*3+0)*SS + s] = cx;
            out1[(b*3+1)*SS + s] = cy;
            out1[(b*3+2)*SS + s] = cz;
        }
        int cnt = 0;
        for (int chunk = 0; chunk < NN/32; chunk++) {
            int j = chunk*32 + lane;
            float dx = __fsub_rn(sx[j], cx);
            float dy = __fsub_rn(sy[j], cy);
            float dz = __fsub_rn(sz[j], cz);
            float d2 = __fadd_rn(__fadd_rn(__fmul_rn(dx,dx), __fmul_rn(dy,dy)),
                                 __fmul_rn(dz,dz));
            bool hit = (d2 <= R2);
            unsigned mask = __ballot_sync(0xffffffffu, hit);
            if (hit) {
                int pos = cnt + __popc(mask & lmask);
                if (pos < 32) f[pos] = j;
            }
            cnt += __popc(mask);
            if (cnt >= 32) break;
        }
        __syncwarp();
        int j = (lane < cnt) ? f[lane] : f[0];
        __syncwarp();

        float fx = sx[j]-cx, fy = sy[j]-cy, fz = sz[j]-cz;
        float p0 = points[(b*3+0)*NN + j];
        float p1 = points[(b*3+1)*NN + j];
        float p2 = points[(b*3+2)*NN + j];

        size_t base = ((size_t)(b*SS + s)*NSAMP + lane) * 8;
        *(float4*)(g_feat + base)     = make_float4(fx, fy, fz, p0);
        *(float4*)(g_feat + base + 4) = make_float4(p1, p2, 0.f, 0.f);

        float fv[6] = {fx, fy, fz, p0, p1, p2};
        int k = 0;
        #pragma unroll
        for (int c = 0; c < 6; c++) {
            s1[c] += fv[c];
            #pragma unroll
            for (int c2 = 0; c2 <= c; c2++) s2[k++] += fv[c]*fv[c2];
        }
    }

    __shared__ float red[27];
    if (tid < 27) red[tid] = 0.f;
    __syncthreads();
    #pragma unroll
    for (int i = 0; i < 6; i++) {
        float v = s1[i];
        for (int off = 16; off; off >>= 1) v += __shfl_down_sync(0xffffffffu, v, off);
        if (lane == 0) atomicAdd(&red[i], v);
    }
    #pragma unroll
    for (int i = 0; i < 21; i++) {
        float v = s2[i];
        for (int off = 16; off; off >>= 1) v += __shfl_down_sync(0xffffffffu, v, off);
        if (lane == 0) atomicAdd(&red[6+i], v);
    }
    __syncthreads();
    if (tid < 6)       atomicAdd(&g_fsum[tid], red[tid]);
    else if (tid < 27) atomicAdd(&g_fmom[tid-6], red[tid]);
}

// ---------------- BN1 fold helper ----------------
static __device__ __forceinline__ void bn1_fold_block(
        const float* __restrict__ W1, const float* __restrict__ g1,
        const float* __restrict__ b1, float* sW1, float* sB1,
        float* sMu, float* sC, int t) {
    if (t == 0) {
        const float inv = 1.0f / (float)NSAMPLES;
        for (int c = 0; c < 6; c++) sMu[c] = g_fsum[c]*inv;
        int k = 0;
        for (int c = 0; c < 6; c++)
            for (int c2 = 0; c2 <= c; c2++) {
                float v = g_fmom[k++]*inv; sC[c*6+c2] = v; sC[c2*6+c] = v;
            }
    }
    __syncthreads();
    if (t < 64) {
        float w[6];
        #pragma unroll
        for (int c = 0; c < 6; c++) w[c] = W1[t*6+c];
        float mean = 0.f;
        #pragma unroll
        for (int c = 0; c < 6; c++) mean += w[c]*sMu[c];
        float e2 = 0.f;
        #pragma unroll
        for (int c = 0; c < 6; c++) {
            float tt = 0.f;
            #pragma unroll
            for (int c2 = 0; c2 < 6; c2++) tt += sC[c*6+c2]*w[c2];
            e2 += w[c]*tt;
        }
        float var = fmaxf(e2 - mean*mean, 0.f);
        float sc = g1[t]*rsqrtf(var + BNEPS);
        #pragma unroll
        for (int c = 0; c < 6; c++) sW1[t*6+c] = w[c]*sc;
        sB1[t] = b1[t] - mean*sc;
    }
    __syncthreads();
}

// ---------------- K2: stats — h1 -> GEMM1 -> moments + store raw x2 fp16 -----
#define SM2_W2H 4096
#define SM2_HB  12288
#define SM2_TOTAL 28672
__global__ __launch_bounds__(256) void k_stats(const float* __restrict__ W1,
                                               const float* __restrict__ g1,
                                               const float* __restrict__ b1,
                                               const float* __restrict__ W2,
                                               const float* __restrict__ g2,
                                               const float* __restrict__ b2) {
    extern __shared__ float smf[];
    char* smc = (char*)smf;
    uint32_t sbase = smem_to_u32(smc);
    float* sW1  = smf;          // 384
    float* sB1  = smf + 384;    // 64
    float* sMu  = smf + 448;    // 6
    float* sC   = smf + 454;    // 36
    float* csum = smf + 512;    // 64
    float* csq  = smf + 576;    // 64

    int t = threadIdx.x, w = t >> 5, lane = t & 31;
    if (t < 64) { csum[t] = 0.f; csq[t] = 0.f; }
    bn1_fold_block(W1, g1, b1, sW1, sB1, sMu, sC, t);

    for (int i = t; i < 2048; i += 256) {
        int o = i >> 5, kk = (i & 31)*2;
        __half2 hv = __floats2half2_rn(W2[o*64 + kk], W2[o*64 + kk + 1]);
        *(uint32_t*)(smc + SM2_W2H + swz((uint32_t)(o*128 + kk*2))) = *(uint32_t*)&hv;
    }
    __syncthreads();

    int m0 = w*16;
    uint32_t hbB = sbase + SM2_HB, w2B = sbase + SM2_W2H;
    int arow = m0 + (lane & 15);
    int acolb = ((lane >> 4) & 1) * 16;
    int b4row = ((lane >> 4) << 3) + (lane & 7);
    int b4colb = ((lane >> 3) & 1) * 16;
    int srow = w*16 + (lane >> 1), kb = lane & 1;
    int r0 = m0 + (lane >> 2);

    float psum[16], pqsum[16];
    #pragma unroll
    for (int i = 0; i < 16; i++) { psum[i] = 0.f; pqsum[i] = 0.f; }

    for (int tile = blockIdx.x; tile < NTILES; tile += gridDim.x) {
        size_t s0 = (size_t)tile * 128;
        // build fp16 h1 (own rows)
        {
            const float* fp = g_feat + (s0 + srow)*8;
            float4 f0 = *(const float4*)fp;
            float4 f1 = *(const float4*)(fp + 4);
            float f[6] = {f0.x, f0.y, f0.z, f0.w, f1.x, f1.y};
            #pragma unroll
            for (int m = 0; m < 4; m++) {
                uint32_t pk[4];
                #pragma unroll
                for (int q = 0; q < 4; q++) {
                    int k = kb*32 + m*8 + q*2;
                    float a0 = sB1[k], a1 = sB1[k+1];
                    #pragma unroll
                    for (int c = 0; c < 6; c++) {
                        a0 += f[c]*sW1[k*6+c];
                        a1 += f[c]*sW1[(k+1)*6+c];
                    }
                    __half2 hv = __floats2half2_rn(fmaxf(a0, 0.f), fmaxf(a1, 0.f));
                    pk[q] = *(uint32_t*)&hv;
                }
                *(uint4*)(smc + SM2_HB + swz((uint32_t)(srow*128 + kb*64 + m*16))) =
                    make_uint4(pk[0], pk[1], pk[2], pk[3]);
            }
        }
        __syncwarp();
        // GEMM1: x2 = h1 · W2^T (A reads own rows only)
        float acc[8][4];
        #pragma unroll
        for (int j = 0; j < 8; j++)
            #pragma unroll
            for (int i = 0; i < 4; i++) acc[j][i] = 0.f;
        #pragma unroll
        for (int ks = 0; ks < 4; ks++) {
            int k0b = ks*32;
            uint32_t a[4];
            ldsm_x4(a, hbB + swz((uint32_t)(arow*128 + k0b + acolb)));
            #pragma unroll
            for (int u = 0; u < 4; u++) {
                uint32_t b4[4];
                ldsm_x4(b4, w2B + swz((uint32_t)((u*16 + b4row)*128 + k0b + b4colb)));
                uint32_t b0[2] = {b4[0], b4[1]};
                uint32_t b1v[2] = {b4[2], b4[3]};
                mma16816(acc[2*u],   a, b0);
                mma16816(acc[2*u+1], a, b1v);
            }
        }
        // moments (register-resident)
        #pragma unroll
        for (int j = 0; j < 8; j++) {
            float d0 = acc[j][0], d1 = acc[j][1], d2 = acc[j][2], d3 = acc[j][3];
            psum[2*j]    += d0 + d2;
            psum[2*j+1]  += d1 + d3;
            pqsum[2*j]   += d0*d0 + d2*d2;
            pqsum[2*j+1] += d1*d1 + d3*d3;
        }
        __syncwarp();
        // write raw x2 fp16 into own rows (overwrites h1)
        #pragma unroll
        for (int j = 0; j < 8; j++) {
            int o = 8*j + 2*(lane & 3);
            __half2 h01 = __floats2half2_rn(acc[j][0], acc[j][1]);
            __half2 h23 = __floats2half2_rn(acc[j][2], acc[j][3]);
            *(uint32_t*)(smc + SM2_HB + swz((uint32_t)(r0*128 + o*2)))     = *(uint32_t*)&h01;
            *(uint32_t*)(smc + SM2_HB + swz((uint32_t)((r0+8)*128 + o*2))) = *(uint32_t*)&h23;
        }
        __syncwarp();
        // copy own 2KB (rows m0..m0+15, raw-swizzled) to global
        {
            char* dst = (char*)g_x2h + (size_t)tile*16384 + (size_t)m0*128;
            const char* src = smc + SM2_HB + m0*128;
            #pragma unroll
            for (int i = lane*16; i < 2048; i += 512)
                *(uint4*)(dst + i) = *(const uint4*)(src + i);
        }
        __syncwarp();
    }

    // butterfly + combine + flush
    #pragma unroll
    for (int j = 0; j < 8; j++) {
        float ps0 = psum[2*j], ps1 = psum[2*j+1];
        float pq0 = pqsum[2*j], pq1 = pqsum[2*j+1];
        #pragma unroll
        for (int off = 4; off < 32; off <<= 1) {
            ps0 += __shfl_xor_sync(0xffffffffu, ps0, off);
            ps1 += __shfl_xor_sync(0xffffffffu, ps1, off);
            pq0 += __shfl_xor_sync(0xffffffffu, pq0, off);
            pq1 += __shfl_xor_sync(0xffffffffu, pq1, off);
        }
        if (lane < 4) {
            int o = 8*j + 2*lane;
            atomicAdd(&csum[o],   ps0);
            atomicAdd(&csum[o+1], ps1);
            atomicAdd(&csq[o],    pq0);
            atomicAdd(&csq[o+1],  pq1);
        }
    }
    __syncthreads();
    if (t < 64) { atomicAdd(&g_x2s[t], csum[t]); atomicAdd(&g_x2q[t], csq[t]); }

    // ---- last-block BN2 tail ----
    __threadfence();
    __syncthreads();
    __shared__ unsigned amLast;
    if (t == 0) amLast = (atomicAdd(&g_cnt, 1u) == gridDim.x - 1u) ? 1u : 0u;
    __syncthreads();
    if (!amLast) return;

    if (t < 64) {
        const float inv = 1.0f / (float)NSAMPLES;
        float m  = __ldcg(&g_x2s[t]) * inv;
        float qv = __ldcg(&g_x2q[t]) * inv;
        float var = fmaxf(qv - m*m, 0.f);
        float sc = g2[t]*rsqrtf(var + BNEPS);
        g_sc2[t] = sc; g_sh2[t] = b2[t] - m*sc;
    }
}

// ---------------- K3: GEMM2-only HMMA layer (x2 streamed from global) --------
#define SMX_W3H 4096
#define SMX_HB  20480
#define SMX_RMX 36864
#define SMX_RMN 40960
#define SMX_TOTAL 45056

__global__ __launch_bounds__(256, 3) void k_mma(const float* __restrict__ W3) {
    extern __shared__ char smc[];
    float* smf = (float*)smc;
    uint32_t sbase = smem_to_u32(smc);
    int t = threadIdx.x, w = t >> 5, lane = t & 31;

    float* sc2s = smf;          // 64
    float* sh2s = smf + 64;     // 64
    float* csum = smf + 128;    // 128
    float* csq  = smf + 256;    // 128
    float* rmax = (float*)(smc + SMX_RMX);
    float* rmin = (float*)(smc + SMX_RMN);

    if (t < 64) { sc2s[t] = g_sc2[t]; sh2s[t] = g_sh2[t]; }
    if (t < 128){ csum[t] = 0.f; csq[t] = 0.f; }
    for (int i = t; i < 4096; i += 256) {
        int o = i >> 5, kk = (i & 31)*2;
        __half2 hv = __floats2half2_rn(W3[o*64 + kk], W3[o*64 + kk + 1]);
        *(uint32_t*)(smc + SMX_W3H + swz((uint32_t)(o*128 + kk*2))) = *(uint32_t*)&hv;
    }
    __syncthreads();    // sc2s/sh2s visible to all for bn2-on-load

    size_t s0 = (size_t)blockIdx.x * 128;

    // stream x2 tile, apply bn2+relu, store fp16 h2 (layout preserved)
    {
        const char* src = (const char*)g_x2h + s0*128;
        #pragma unroll 2
        for (int off = t*16; off < 16384; off += 256*16) {
            uint4 v = *(const uint4*)(src + off);
            uint32_t logical = swz((uint32_t)off);
            int ch = (int)(logical & 127) >> 1;
            uint32_t pk[4] = {v.x, v.y, v.z, v.w};
            #pragma unroll
            for (int q = 0; q < 4; q++) {
                __half2 hp = *(__half2*)&pk[q];
                float2 f = __half22float2(hp);
                int o = ch + q*2;
                f.x = fmaxf(f.x*sc2s[o]   + sh2s[o],   0.f);
                f.y = fmaxf(f.y*sc2s[o+1] + sh2s[o+1], 0.f);
                __half2 r = __floats2half2_rn(f.x, f.y);
                pk[q] = *(uint32_t*)&r;
            }
            *(uint4*)(smc + SMX_HB + off) = make_uint4(pk[0], pk[1], pk[2], pk[3]);
        }
    }
    __syncthreads();

    int m0 = w*16;
    uint32_t hbB = sbase + SMX_HB, w3B = sbase + SMX_W3H;
    int arow = m0 + (lane & 15);
    int acolb = ((lane >> 4) & 1) * 16;
    int b4row = ((lane >> 4) << 3) + (lane & 7);
    int b4colb = ((lane >> 3) & 1) * 16;

    // GEMM2: two passes of 8 n-tiles
    #pragma unroll 1
    for (int half = 0; half < 2; half++) {
        float acc[8][4];
        #pragma unroll
        for (int j = 0; j < 8; j++)
            #pragma unroll
            for (int i = 0; i < 4; i++) acc[j][i] = 0.f;
        uint32_t w3half = w3B + (uint32_t)half*8192;
        #pragma unroll
        for (int ks = 0; ks < 4; ks++) {
            int k0b = ks*32;
            uint32_t a[4];
            ldsm_x4(a, hbB + swz((uint32_t)(arow*128 + k0b + acolb)));
            #pragma unroll
            for (int u = 0; u < 4; u++) {
                uint32_t b4[4];
                ldsm_x4(b4, w3half + swz((uint32_t)((u*16 + b4row)*128 + k0b + b4colb)));
                uint32_t b0[2] = {b4[0], b4[1]};
                uint32_t b1[2] = {b4[2], b4[3]};
                mma16816(acc[2*u],   a, b0);
                mma16816(acc[2*u+1], a, b1);
            }
        }
        #pragma unroll
        for (int j = 0; j < 8; j++) {
            float d0 = acc[j][0], d1 = acc[j][1], d2 = acc[j][2], d3 = acc[j][3];
            float mx0 = fmaxf(d0, d2), mx1 = fmaxf(d1, d3);
            float mn0 = fminf(d0, d2), mn1 = fminf(d1, d3);
            float ps0 = d0 + d2, ps1 = d1 + d3;
            float pq0 = d0*d0 + d2*d2, pq1 = d1*d1 + d3*d3;
            #pragma unroll
            for (int off = 4; off < 32; off <<= 1) {
                mx0 = fmaxf(mx0, __shfl_xor_sync(0xffffffffu, mx0, off));
                mx1 = fmaxf(mx1, __shfl_xor_sync(0xffffffffu, mx1, off));
                mn0 = fminf(mn0, __shfl_xor_sync(0xffffffffu, mn0, off));
                mn1 = fminf(mn1, __shfl_xor_sync(0xffffffffu, mn1, off));
                ps0 += __shfl_xor_sync(0xffffffffu, ps0, off);
                ps1 += __shfl_xor_sync(0xffffffffu, ps1, off);
                pq0 += __shfl_xor_sync(0xffffffffu, pq0, off);
                pq1 += __shfl_xor_sync(0xffffffffu, pq1, off);
            }
            if (lane < 4) {
                int o = half*64 + 8*j + 2*lane;
                rmax[w*128 + o]     = mx0;
                rmax[w*128 + o + 1] = mx1;
                rmin[w*128 + o]     = mn0;
                rmin[w*128 + o + 1] = mn1;
                atomicAdd(&csum[o],   ps0);
                atomicAdd(&csum[o+1], ps1);
                atomicAdd(&csq[o],    pq0);
                atomicAdd(&csq[o+1],  pq1);
            }
        }
    }
    __syncthreads();

    for (int v = t; v < 512; v += 256) {
        int g = v >> 7, o = v & 127;
        float mx = fmaxf(rmax[(2*g)*128 + o], rmax[(2*g+1)*128 + o]);
        float mn = fminf(rmin[(2*g)*128 + o], rmin[(2*g+1)*128 + o]);
        g_gmax[(s0/32 + g)*128 + o] = mx;
        g_gmin[(s0/32 + g)*128 + o] = mn;
    }
    if (t < 128) { atomicAdd(&g_x3sum[t], csum[t]); atomicAdd(&g_x3sq[t], csq[t]); }
}

// ---------------- K4: bn3 (inline) + relu on group max/min, transposed out ----
__global__ void k_out2(const float* __restrict__ g3, const float* __restrict__ b3,
                       float* __restrict__ out2) {
    __shared__ float tr[32*129];
    __shared__ float ssc[128], ssh[128];
    int b = blockIdx.y;
    int s0 = blockIdx.x * 32;
    int t = threadIdx.x;
    if (t < 128) {
        const float inv = 1.0f / (float)NSAMPLES;
        float m = g_x3sum[t]*inv;
        float v = fmaxf(g_x3sq[t]*inv - m*m, 0.f);
        float sc = g3[t]*rsqrtf(v + BNEPS);
        ssc[t] = sc; ssh[t] = b3[t] - m*sc;
    }
    __syncthreads();
    for (int i = t; i < 32*128; i += 256) {
        int gi = i >> 7, o = i & 127;
        float sc = ssc[o], sh = ssh[o];
        size_t g = (size_t)(b*SS + s0 + gi);
        float v = (sc >= 0.f) ? g_gmax[g*128 + o] : g_gmin[g*128 + o];
        tr[gi*129 + o] = fmaxf(sc*v + sh, 0.f);
    }
    __syncthreads();
    for (int i = t; i < 32*128; i += 256) {
        int o = i >> 5, si = i & 31;
        out2[((size_t)(b*128 + o))*SS + s0 + si] = tr[si*129 + o];
    }
}

// ---------------- launch ----------------
extern "C" void kernel_launch(void* const* d_in, const int* in_sizes, int n_in,
                              void* d_out, int out_size) {
    const float* xyz    = (const float*)d_in[0];
    const float* points = (const float*)d_in[1];
    const int*   fps    = (const int*)  d_in[2];
    const float* W1 = (const float*)d_in[3];
    const float* g1 = (const float*)d_in[4];
    const float* b1 = (const float*)d_in[5];
    const float* W2 = (const float*)d_in[6];
    const float* g2 = (const float*)d_in[7];
    const float* b2 = (const float*)d_in[8];
    const float* W3 = (const float*)d_in[9];
    const float* g3 = (const float*)d_in[10];
    const float* b3 = (const float*)d_in[11];

    float* out1 = (float*)d_out;
    float* out2 = (float*)d_out + (size_t)BB*3*SS;

    const int SMEM_BALL  = (3*NN)*4 + 8*32*4;

    cudaFuncSetAttribute(k_ball,  cudaFuncAttributeMaxDynamicSharedMemorySize, SMEM_BALL);
    cudaFuncSetAttribute(k_stats, cudaFuncAttributeMaxDynamicSharedMemorySize, SM2_TOTAL);
    cudaFuncSetAttribute(k_mma,   cudaFuncAttributeMaxDynamicSharedMemorySize, SMX_TOTAL);

    k_zero<<<1, 256>>>();
    k_ball<<<dim3(SS/32, BB), 256, SMEM_BALL>>>(xyz, points, fps, out1);
    k_stats<<<592, 256, SM2_TOTAL>>>(W1, g1, b1, W2, g2, b2);
    k_mma<<<NTILES, 256, SMX_TOTAL>>>(W3);
    k_out2<<<dim3(SS/32, BB), 256>>>(g3, b3, out2);
}